// round 5
// baseline (speedup 1.0000x reference)
#include <cuda_runtime.h>
#include <cstdint>

// Problem constants
#define PD 128   // D (feature dim)
#define PP 64    // P (points per polygon)
#define HS 132   // padded smem row stride (bank-conflict-free broadcast)
#define NLAYER 3

#ifndef USE_F32X2
#define USE_F32X2 1
#endif

typedef unsigned long long ull;

struct SmemT {
  float hA[2 * PP * HS];      // layer input / GEMM2 output (per poly)
  float hB[2 * PP * HS];      // GEMM1 (post-LN/ReLU) output
  float Wb[PD * PD];          // staged weight matrix (shared by both polys)
  float aggsm[2][PD];         // masked max over P
  float aggw[2][PD];          // b2 + agg @ W2_bottom  (per-poly broadcast row)
  float b1s[PD];
  float gs[PD];
  float bs[PD];
  unsigned char validsm[2][PP];
  int pv[2];                  // poly has >=1 valid point
  unsigned int det[2];        // mask-dtype detection ORs
};

#if USE_F32X2
__device__ __forceinline__ ull pk2(float lo, float hi) {
  ull r; asm("mov.b64 %0, {%1, %2};" : "=l"(r) : "f"(lo), "f"(hi)); return r;
}
__device__ __forceinline__ float2 up2(ull v) {
  float2 r; asm("mov.b64 {%0, %1}, %2;" : "=f"(r.x), "=f"(r.y) : "l"(v)); return r;
}
__device__ __forceinline__ void fma2(ull& d, ull a, ull b) {
  asm("fma.rn.f32x2 %0, %1, %2, %3;" : "=l"(d) : "l"(a), "l"(b), "l"(d));
}
typedef ull acc_t;
#else
typedef float2 acc_t;
__device__ __forceinline__ float2 pk2(float lo, float hi) { return make_float2(lo, hi); }
__device__ __forceinline__ float2 up2(float2 v) { return v; }
__device__ __forceinline__ void fma2(float2& d, float2 a, float2 b) {
  d.x = fmaf(a.x, b.x, d.x); d.y = fmaf(a.y, b.y, d.y);
}
#endif

// 64x128x128 GEMM over one polygon's tile; thread tile 8p x 8e.
// initv[e] is the per-column accumulator init (bias for GEMM1, aggW for GEMM2).
template<bool DO_LN>
__device__ __forceinline__ void gemm_block(
    const float* __restrict__ hin, float* __restrict__ hout,
    const float* __restrict__ Wb, const float* __restrict__ initv,
    const float* __restrict__ gs, const float* __restrict__ bs,
    int p0, int e0)
{
  acc_t acc[8][4];
  {
    float4 i0 = *reinterpret_cast<const float4*>(&initv[e0]);
    float4 i1 = *reinterpret_cast<const float4*>(&initv[e0 + 4]);
    acc_t c0 = pk2(i0.x, i0.y), c1 = pk2(i0.z, i0.w);
    acc_t c2 = pk2(i1.x, i1.y), c3 = pk2(i1.z, i1.w);
    #pragma unroll
    for (int i = 0; i < 8; i++) { acc[i][0]=c0; acc[i][1]=c1; acc[i][2]=c2; acc[i][3]=c3; }
  }
  #pragma unroll 2
  for (int d0 = 0; d0 < PD; d0 += 2) {
    float2 hv[8];
    #pragma unroll
    for (int i = 0; i < 8; i++)
      hv[i] = *reinterpret_cast<const float2*>(&hin[(p0 + i) * HS + d0]);
    #pragma unroll
    for (int jd = 0; jd < 2; jd++) {
      const float* wr = &Wb[(d0 + jd) * PD + e0];
      float4 w0 = *reinterpret_cast<const float4*>(wr);
      float4 w1 = *reinterpret_cast<const float4*>(wr + 4);
      acc_t wa0 = pk2(w0.x, w0.y), wa1 = pk2(w0.z, w0.w);
      acc_t wb0 = pk2(w1.x, w1.y), wb1 = pk2(w1.z, w1.w);
      #pragma unroll
      for (int i = 0; i < 8; i++) {
        float hs = jd ? hv[i].y : hv[i].x;
        acc_t hp = pk2(hs, hs);
        fma2(acc[i][0], hp, wa0);
        fma2(acc[i][1], hp, wa1);
        fma2(acc[i][2], hp, wb0);
        fma2(acc[i][3], hp, wb1);
      }
    }
  }
  if (DO_LN) {
    float4 g0 = *reinterpret_cast<const float4*>(&gs[e0]);
    float4 g1 = *reinterpret_cast<const float4*>(&gs[e0 + 4]);
    float4 t0 = *reinterpret_cast<const float4*>(&bs[e0]);
    float4 t1 = *reinterpret_cast<const float4*>(&bs[e0 + 4]);
    #pragma unroll
    for (int i = 0; i < 8; i++) {
      float2 v0 = up2(acc[i][0]), v1 = up2(acc[i][1]);
      float2 v2 = up2(acc[i][2]), v3 = up2(acc[i][3]);
      float s = (v0.x + v0.y) + (v1.x + v1.y) + (v2.x + v2.y) + (v3.x + v3.y);
      float q = (v0.x*v0.x + v0.y*v0.y) + (v1.x*v1.x + v1.y*v1.y)
              + (v2.x*v2.x + v2.y*v2.y) + (v3.x*v3.x + v3.y*v3.y);
      // full-row (128-wide) reduction lives in the 16-lane group that owns row p
      #pragma unroll
      for (int m = 8; m >= 1; m >>= 1) {
        s += __shfl_xor_sync(0xffffffffu, s, m);
        q += __shfl_xor_sync(0xffffffffu, q, m);
      }
      float mean = s * (1.0f / 128.0f);
      float var  = fmaf(q, 1.0f / 128.0f, -mean * mean);
      float inv  = rsqrtf(var + 1e-5f);
      float4 o0, o1;
      o0.x = fmaxf(fmaf((v0.x - mean) * inv, g0.x, t0.x), 0.f);
      o0.y = fmaxf(fmaf((v0.y - mean) * inv, g0.y, t0.y), 0.f);
      o0.z = fmaxf(fmaf((v1.x - mean) * inv, g0.z, t0.z), 0.f);
      o0.w = fmaxf(fmaf((v1.y - mean) * inv, g0.w, t0.w), 0.f);
      o1.x = fmaxf(fmaf((v2.x - mean) * inv, g1.x, t1.x), 0.f);
      o1.y = fmaxf(fmaf((v2.y - mean) * inv, g1.y, t1.y), 0.f);
      o1.z = fmaxf(fmaf((v3.x - mean) * inv, g1.z, t1.z), 0.f);
      o1.w = fmaxf(fmaf((v3.y - mean) * inv, g1.w, t1.w), 0.f);
      *reinterpret_cast<float4*>(&hout[(p0 + i) * HS + e0])     = o0;
      *reinterpret_cast<float4*>(&hout[(p0 + i) * HS + e0 + 4]) = o1;
    }
  } else {
    #pragma unroll
    for (int i = 0; i < 8; i++) {
      float2 v0 = up2(acc[i][0]), v1 = up2(acc[i][1]);
      float2 v2 = up2(acc[i][2]), v3 = up2(acc[i][3]);
      float4 o0, o1;
      o0.x = v0.x; o0.y = v0.y; o0.z = v1.x; o0.w = v1.y;
      o1.x = v2.x; o1.y = v2.y; o1.z = v3.x; o1.w = v3.y;
      *reinterpret_cast<float4*>(&hout[(p0 + i) * HS + e0])     = o0;
      *reinterpret_cast<float4*>(&hout[(p0 + i) * HS + e0 + 4]) = o1;
    }
  }
}

__device__ __forceinline__ void copy_w(float* __restrict__ dst,
                                       const float* __restrict__ src, int tid) {
  const float4* s = reinterpret_cast<const float4*>(src);
  float4* d = reinterpret_cast<float4*>(dst);
  #pragma unroll
  for (int i = tid; i < PD * PD / 4; i += 256) d[i] = s[i];
}

__global__ void __launch_bounds__(256, 1) polynet_kernel(
    const float* __restrict__ x, const uint8_t* __restrict__ mask,
    const float* __restrict__ W1, const float* __restrict__ b1,
    const float* __restrict__ lng, const float* __restrict__ lnb,
    const float* __restrict__ W2, const float* __restrict__ b2,
    float* __restrict__ out)
{
  extern __shared__ char smraw[];
  SmemT& sm = *reinterpret_cast<SmemT*>(smraw);
  const int tid = threadIdx.x;
  const int g0 = blockIdx.x * 2;   // 2 polygons per CTA

  if (tid < 2) { sm.pv[tid] = 0; sm.det[tid] = 0u; }
  __syncthreads();

  // ---- mask dtype detection over first 4096 bytes (safe in all layouts) ----
  {
    const unsigned int* mw = reinterpret_cast<const unsigned int*>(mask);
    unsigned int o0 = 0, o123 = 0, o23 = 0;
    #pragma unroll 2
    for (int j = tid; j < 1024; j += 256) {
      unsigned int w = mw[j];
      o0   |=  w        & 0xffu;
      o123 |= (w >>  8);
      o23  |= (w >> 16);
    }
    (void)o0;
    if (o123) atomicOr(&sm.det[0], o123 & 0xffffffu);
    if (o23)  atomicOr(&sm.det[1], o23  & 0xffffu);
  }
  __syncthreads();
  // mode: 0 = 1-byte bool, 1 = 4-byte (int32 or float32; word != 0 test)
  const int mmode = (sm.det[1] & 0xF0F0u) ? 1 : (sm.det[0] ? 0 : 1);

  if (tid < 128) {
    int lp = tid >> 6, p = tid & 63;
    int midx = (g0 + lp) * PP + p;
    uint8_t m;
    if (mmode == 0) m = mask[midx] ? 1 : 0;          // 1-byte bool
    else m = (reinterpret_cast<const unsigned int*>(mask)[midx] != 0u) ? 1 : 0;
    sm.validsm[lp][p] = m;                           // True == valid point
    if (m) atomicOr(&sm.pv[lp], 1);
  }
  __syncthreads();
  if (tid < 128) {
    int lp = tid >> 6, p = tid & 63;
    if (!sm.pv[lp]) sm.validsm[lp][p] = 1;  // neutralize fully-invalid poly (ref semantics)
  }

  // Load x tile(s); zero features for fully-invalid polygons.
  {
    int pv0 = sm.pv[0], pv1 = sm.pv[1];
    #pragma unroll 4
    for (int i = tid; i < 4096; i += 256) {        // 4096 float4 = 2 polys * 64 * 128
      int lp  = i >> 11;
      int rem = i & 2047;
      int p   = rem >> 5;
      int dv  = rem & 31;
      float4 v = make_float4(0.f, 0.f, 0.f, 0.f);
      if (lp ? pv1 : pv0)
        v = *reinterpret_cast<const float4*>(
              &x[(((size_t)(g0 + lp)) * PP + p) * PD + dv * 4]);
      *reinterpret_cast<float4*>(&sm.hA[lp * PP * HS + p * HS + dv * 4]) = v;
    }
  }

  const int lpoly = tid >> 7;        // which of the 2 polygons this thread computes
  const int t  = tid & 127;
  const int ty = t >> 4;             // p-tile (8 rows)
  const int tx = t & 15;             // e-tile (8 cols)
  const int e0 = tx * 8;
  const int p0 = ty * 8;
  float* hA = &sm.hA[lpoly * PP * HS];
  float* hB = &sm.hB[lpoly * PP * HS];

  const int ecol = tid & 127;        // column ownership for agg/output phases
  const int cpol = tid >> 7;

  for (int l = 0; l < NLAYER; l++) {
    __syncthreads();
    copy_w(sm.Wb, W1 + (size_t)l * PD * PD, tid);
    if (tid < PD) {
      sm.b1s[tid] = b1[l * PD + tid];
      sm.gs[tid]  = lng[l * PD + tid];
      sm.bs[tid]  = lnb[l * PD + tid];
    }
    __syncthreads();

    gemm_block<true>(hA, hB, sm.Wb, sm.b1s, sm.gs, sm.bs, p0, e0);
    __syncthreads();

    // agg[e] = max over valid p of hB[p][e]; meanwhile stage W2 top half
    {
      const float* hb = &sm.hB[cpol * PP * HS];
      float m = -3.402823e38f;
      #pragma unroll 8
      for (int p = 0; p < PP; p++)
        if (sm.validsm[cpol][p]) m = fmaxf(m, hb[p * HS + ecol]);
      sm.aggsm[cpol][ecol] = m;
    }
    copy_w(sm.Wb, W2 + (size_t)l * 2 * PD * PD, tid);
    __syncthreads();

    // aggw[e] = b2[e] + sum_d agg[d] * W2_bottom[d][e]  (shared by all 64 points)
    {
      const float* w2bot = W2 + (size_t)l * 2 * PD * PD + PD * PD;
      float a = b2[l * PD + ecol];
      #pragma unroll 8
      for (int d = 0; d < PD; d++)
        a = fmaf(sm.aggsm[cpol][d], __ldg(&w2bot[d * PD + ecol]), a);
      sm.aggw[cpol][ecol] = a;
    }
    __syncthreads();

    gemm_block<false>(hB, hA, sm.Wb, sm.aggw[lpoly], sm.gs, sm.bs, p0, e0);
  }
  __syncthreads();

  // Final masked max over P, zero for fully-invalid polys.
  {
    const float* ha = &sm.hA[cpol * PP * HS];
    float m = -3.402823e38f;
    #pragma unroll 8
    for (int p = 0; p < PP; p++)
      if (sm.validsm[cpol][p]) m = fmaxf(m, ha[p * HS + ecol]);
    if (!sm.pv[cpol]) m = 0.f;
    out[(size_t)(g0 + cpol) * PD + ecol] = m;
  }
}

extern "C" void kernel_launch(void* const* d_in, const int* in_sizes, int n_in,
                              void* d_out, int out_size) {
  const float*   x    = (const float*)d_in[0];
  const uint8_t* mask = (const uint8_t*)d_in[1];
  const float*   W1   = (const float*)d_in[2];
  const float*   b1   = (const float*)d_in[3];
  const float*   lng  = (const float*)d_in[4];
  const float*   lnb  = (const float*)d_in[5];
  const float*   W2   = (const float*)d_in[6];
  const float*   b2   = (const float*)d_in[7];
  float* out = (float*)d_out;

  // idempotent, deterministic, not a stream op -> safe under graph capture
  (void)cudaFuncSetAttribute(polynet_kernel,
                             cudaFuncAttributeMaxDynamicSharedMemorySize,
                             (int)sizeof(SmemT));
  polynet_kernel<<<1024, 256, sizeof(SmemT)>>>(x, mask, W1, b1, lng, lnb, W2, b2, out);
}

// round 7
// speedup vs baseline: 1.6428x; 1.6428x over previous
#include <cuda_runtime.h>
#include <cuda_bf16.h>
#include <cstdint>

#define NL 3
#define AST 136                      // padded row stride (bf16 elems), conflict-free ldmatrix
#define NEG_BIG (-3.402823466e38f)

typedef unsigned int u32;
typedef unsigned short u16;

// Pre-split weight images: [l*2+m][hi=0/lo=1][n*AST + k], bf16, [n][k] layout (col-major KxN)
__device__ __align__(16) u16 g_Bimg[NL * 2][2][128 * AST];

__device__ __forceinline__ u32 smaddr(const void* p) {
  u32 a; asm("{ .reg .u64 t; cvta.to.shared.u64 t, %1; cvt.u32.u64 %0, t; }"
             : "=r"(a) : "l"(p));
  return a;
}
__device__ __forceinline__ void ldsm4(u32& r0, u32& r1, u32& r2, u32& r3, u32 a) {
  asm volatile("ldmatrix.sync.aligned.m8n8.x4.shared.b16 {%0,%1,%2,%3}, [%4];"
               : "=r"(r0), "=r"(r1), "=r"(r2), "=r"(r3) : "r"(a));
}
__device__ __forceinline__ void mmab(float* c, u32 a0, u32 a1, u32 a2, u32 a3,
                                     u32 b0, u32 b1) {
  asm volatile(
    "mma.sync.aligned.m16n8k16.row.col.f32.bf16.bf16.f32 "
    "{%0,%1,%2,%3}, {%4,%5,%6,%7}, {%8,%9}, {%0,%1,%2,%3};"
    : "+f"(c[0]), "+f"(c[1]), "+f"(c[2]), "+f"(c[3])
    : "r"(a0), "r"(a1), "r"(a2), "r"(a3), "r"(b0), "r"(b1));
}
__device__ __forceinline__ void cpa16(u32 dst, const void* src) {
  asm volatile("cp.async.cg.shared.global [%0], [%1], 16;" :: "r"(dst), "l"(src) : "memory");
}
#define CP_COMMIT() asm volatile("cp.async.commit_group;" ::: "memory")
#define CP_WAIT1()  asm volatile("cp.async.wait_group 1;" ::: "memory")
#define CP_WAIT0()  asm volatile("cp.async.wait_group 0;" ::: "memory")

__device__ __forceinline__ void split2(float f0, float f1, u32& hp, u32& lp) {
  __nv_bfloat16 h0 = __float2bfloat16(f0), h1 = __float2bfloat16(f1);
  float l0 = f0 - __bfloat162float(h0), l1 = f1 - __bfloat162float(h1);
  __nv_bfloat16 q0 = __float2bfloat16(l0), q1 = __float2bfloat16(l1);
  hp = (u32)__bfloat16_as_ushort(h0) | ((u32)__bfloat16_as_ushort(h1) << 16);
  lp = (u32)__bfloat16_as_ushort(q0) | ((u32)__bfloat16_as_ushort(q1) << 16);
}

// ---------------- prep: split fp32 weights into bf16 hi/lo [n][k] images ----------------
__global__ void prep_kernel(const float* __restrict__ W1, const float* __restrict__ W2) {
  int id = blockIdx.x * blockDim.x + threadIdx.x;
  if (id >= NL * 2 * 128 * 128) return;
  int n = id & 127, k = (id >> 7) & 127, m = (id >> 14) & 1, l = id >> 15;
  float w = m ? W2[((size_t)l * 256 + k) * 128 + n]
              : W1[((size_t)l * 128 + k) * 128 + n];
  __nv_bfloat16 hi = __float2bfloat16(w);
  __nv_bfloat16 lo = __float2bfloat16(w - __bfloat162float(hi));
  g_Bimg[l * 2 + m][0][n * AST + k] = __bfloat16_as_ushort(hi);
  g_Bimg[l * 2 + m][1][n * AST + k] = __bfloat16_as_ushort(lo);
}

// ---------------- main fused kernel ----------------
struct Sm {
  u16 Ahi[128 * AST];            // 34816 B
  u16 Alo[128 * AST];
  u16 Bbuf[2][2 * 128 * AST];    // [buf][hi|lo] 2 x 69632 B
  float sred[2][128], qred[2][128];
  float pmax[4][128];
  float agg[2][128], aggw[2][128];
  float bias[128], g[128], beta[128];
  unsigned char valid[128];
  int pv[2];
  u32 det[2];
};

__device__ __forceinline__ void copy_B(u32 dst, const u16* src, int tid) {
  const char* s = reinterpret_cast<const char*>(src);
  #pragma unroll
  for (int i = tid; i < 4352; i += 256) cpa16(dst + i * 16, s + (size_t)i * 16);
}

// 3-way split GEMM: acc += Ahi*Bhi + Ahi*Blo + Alo*Bhi, M=128 N=128 K=128
__device__ __forceinline__ void run_gemm(
    float acc[2][8][4], u32 aHi, u32 aLo, u32 bHi, u32 bLo,
    u32 aoff0, u32 aoff1, const u32 boff[4])
{
  #pragma unroll
  for (int s = 0; s < 3; s++) {
    u32 A = (s == 2) ? aLo : aHi;
    u32 B = (s == 1) ? bLo : bHi;
    #pragma unroll
    for (int kt = 0; kt < 8; kt++) {
      u32 a0[4], a1[4], bf[4][4];
      ldsm4(a0[0], a0[1], a0[2], a0[3], A + aoff0 + kt * 32);
      ldsm4(a1[0], a1[1], a1[2], a1[3], A + aoff1 + kt * 32);
      #pragma unroll
      for (int p = 0; p < 4; p++)
        ldsm4(bf[p][0], bf[p][1], bf[p][2], bf[p][3], B + boff[p] + kt * 32);
      #pragma unroll
      for (int nt = 0; nt < 8; nt++) {
        u32 b0 = bf[nt >> 1][(nt & 1) * 2], b1 = bf[nt >> 1][(nt & 1) * 2 + 1];
        mmab(acc[0][nt], a0[0], a0[1], a0[2], a0[3], b0, b1);
        mmab(acc[1][nt], a1[0], a1[1], a1[2], a1[3], b0, b1);
      }
    }
  }
}

__global__ void __launch_bounds__(256, 1) polymma_kernel(
    const float* __restrict__ x, const unsigned char* __restrict__ mask,
    const float* __restrict__ b1, const float* __restrict__ lng,
    const float* __restrict__ lnb, const float* __restrict__ W2,
    const float* __restrict__ b2, float* __restrict__ out)
{
  extern __shared__ unsigned char smraw[];
  uintptr_t sp = (reinterpret_cast<uintptr_t>(smraw) + 127) & ~(uintptr_t)127;
  Sm& sm = *reinterpret_cast<Sm*>(sp);

  const int tid = threadIdx.x;
  const int wid = tid >> 5, lane = tid & 31;
  const int warpM = wid & 3, warpN = wid >> 2;
  const int RB = warpM * 32, CB = warpN * 64;
  const int qr = lane >> 2, qc = lane & 3;
  const int g0 = blockIdx.x * 2;
  const int mypoly = warpM >> 1;         // poly of this warp's rows

  const u32 uAhi = smaddr(sm.Ahi), uAlo = smaddr(sm.Alo);
  const u32 uB0 = smaddr(sm.Bbuf[0]), uB1 = smaddr(sm.Bbuf[1]);

  // ldmatrix per-lane address offsets
  const int arow = (lane & 7) + ((lane >> 3) & 1) * 8;
  const u32 aoff0 = (u32)(((RB + arow) * AST + (lane >> 4) * 8) * 2);
  const u32 aoff1 = aoff0 + 16 * AST * 2;
  u32 boff[4];
  {
    int nrow = (lane & 7) + (lane >> 4) * 8;
    int kcol = ((lane >> 3) & 1) * 8;
    #pragma unroll
    for (int p = 0; p < 4; p++)
      boff[p] = (u32)(((CB + p * 16 + nrow) * AST + kcol) * 2);
  }

  if (tid < 2) { sm.pv[tid] = 0; sm.det[tid] = 0u; }
  __syncthreads();

  // ---- mask dtype detection (proven R5) ----
  {
    const u32* mw = reinterpret_cast<const u32*>(mask);
    u32 o123 = 0, o23 = 0;
    for (int j = tid; j < 1024; j += 256) {
      u32 w = mw[j];
      o123 |= (w >> 8);
      o23  |= (w >> 16);
    }
    if (o123) atomicOr(&sm.det[0], o123 & 0xffffffu);
    if (o23)  atomicOr(&sm.det[1], o23 & 0xffffu);
  }
  __syncthreads();
  const int mmode = (sm.det[1] & 0xF0F0u) ? 1 : (sm.det[0] ? 0 : 1);

  if (tid < 128) {
    int lp = tid >> 6, p = tid & 63;
    int midx = (g0 + lp) * 64 + p;
    unsigned char m;
    if (mmode == 0) m = mask[midx] ? 1 : 0;
    else m = (reinterpret_cast<const u32*>(mask)[midx] != 0u) ? 1 : 0;
    sm.valid[tid] = m;
    if (m) atomicOr(&sm.pv[lp], 1);
  }
  __syncthreads();
  if (tid < 128) {
    if (!sm.pv[tid >> 6]) sm.valid[tid] = 1;   // neutralize fully-invalid poly
  }

  // kick first B copy (layer0 W1) while doing the x prologue
  copy_B(uB0, &g_Bimg[0][0][0], tid);
  CP_COMMIT();

  // ---- prologue: x -> bf16 hi/lo split in A smem ----
  {
    const float4* xs = reinterpret_cast<const float4*>(x + (size_t)g0 * 64 * 128);
    __syncthreads();   // pv ready
    #pragma unroll 4
    for (int i = tid; i < 4096; i += 256) {
      int r = i >> 5, c4 = (i & 31) * 4;
      float4 v = make_float4(0.f, 0.f, 0.f, 0.f);
      if (sm.pv[r >> 6]) v = xs[i];
      u32 h0, l0, h1, l1;
      split2(v.x, v.y, h0, l0);
      split2(v.z, v.w, h1, l1);
      *reinterpret_cast<uint2*>(&sm.Ahi[r * AST + c4]) = make_uint2(h0, h1);
      *reinterpret_cast<uint2*>(&sm.Alo[r * AST + c4]) = make_uint2(l0, l1);
    }
  }

  for (int l = 0; l < NL; l++) {
    if (tid < 128) {
      sm.bias[tid] = b1[l * 128 + tid];
      sm.g[tid]    = lng[l * 128 + tid];
      sm.beta[tid] = lnb[l * 128 + tid];
    }
    // stage W2top of this layer into buf1
    copy_B(uB1, &g_Bimg[l * 2 + 1][0][0], tid);
    CP_COMMIT();
    CP_WAIT1();              // buf0 (W1) ready
    __syncthreads();         // A + B + params visible

    // ---- GEMM1 ----
    float acc[2][8][4];
    #pragma unroll
    for (int a = 0; a < 2; a++)
      #pragma unroll
      for (int b = 0; b < 8; b++)
        #pragma unroll
        for (int e = 0; e < 4; e++) acc[a][b][e] = 0.f;
    run_gemm(acc, uAhi, uAlo, uB0, uB0 + 34816, aoff0, aoff1, boff);

    // ---- epilogue 1: +bias, LN stats ----
    float s[4] = {0.f, 0.f, 0.f, 0.f}, q[4] = {0.f, 0.f, 0.f, 0.f};
    #pragma unroll
    for (int mt = 0; mt < 2; mt++)
      #pragma unroll
      for (int nt = 0; nt < 8; nt++)
        #pragma unroll
        for (int e = 0; e < 4; e++) {
          int c = CB + nt * 8 + qc * 2 + (e & 1);
          float v = acc[mt][nt][e] + sm.bias[c];
          acc[mt][nt][e] = v;
          int rs = mt * 2 + (e >> 1);
          s[rs] += v; q[rs] += v * v;
        }
    #pragma unroll
    for (int rs = 0; rs < 4; rs++) {
      s[rs] += __shfl_xor_sync(0xffffffffu, s[rs], 1);
      s[rs] += __shfl_xor_sync(0xffffffffu, s[rs], 2);
      q[rs] += __shfl_xor_sync(0xffffffffu, q[rs], 1);
      q[rs] += __shfl_xor_sync(0xffffffffu, q[rs], 2);
    }
    if (qc == 0) {
      #pragma unroll
      for (int rs = 0; rs < 4; rs++) {
        int row = RB + (rs >> 1) * 16 + qr + (rs & 1) * 8;
        sm.sred[warpN][row] = s[rs];
        sm.qred[warpN][row] = q[rs];
      }
    }
    __syncthreads();

    // overlap: stage next layer's W1 into buf0 (buf0 free: GEMM1 done by all)
    if (l < NL - 1) { copy_B(uB0, &g_Bimg[(l + 1) * 2][0][0], tid); CP_COMMIT(); }

    float mean[4], inv[4];
    #pragma unroll
    for (int rs = 0; rs < 4; rs++) {
      int row = RB + (rs >> 1) * 16 + qr + (rs & 1) * 8;
      float st = sm.sred[0][row] + sm.sred[1][row];
      float qt = sm.qred[0][row] + sm.qred[1][row];
      mean[rs] = st * (1.f / 128.f);
      inv[rs]  = rsqrtf(fmaf(qt, 1.f / 128.f, -mean[rs] * mean[rs]) + 1e-5f);
    }

    // LN + ReLU, split-store h to A smem, masked col-max partials
    float mx[8][2];
    #pragma unroll
    for (int nt = 0; nt < 8; nt++) { mx[nt][0] = NEG_BIG; mx[nt][1] = NEG_BIG; }
    #pragma unroll
    for (int mt = 0; mt < 2; mt++)
      #pragma unroll
      for (int hi = 0; hi < 2; hi++) {
        int rs = mt * 2 + hi;
        int row = RB + mt * 16 + qr + hi * 8;
        bool val = sm.valid[row] != 0;
        #pragma unroll
        for (int nt = 0; nt < 8; nt++) {
          int c0 = CB + nt * 8 + qc * 2;
          float v0 = acc[mt][nt][2 * hi], v1 = acc[mt][nt][2 * hi + 1];
          float h0 = fmaxf(fmaf((v0 - mean[rs]) * inv[rs], sm.g[c0],     sm.beta[c0]),     0.f);
          float h1 = fmaxf(fmaf((v1 - mean[rs]) * inv[rs], sm.g[c0 + 1], sm.beta[c0 + 1]), 0.f);
          u32 hp, lp; split2(h0, h1, hp, lp);
          *reinterpret_cast<u32*>(&sm.Ahi[row * AST + c0]) = hp;
          *reinterpret_cast<u32*>(&sm.Alo[row * AST + c0]) = lp;
          mx[nt][0] = fmaxf(mx[nt][0], val ? h0 : NEG_BIG);
          mx[nt][1] = fmaxf(mx[nt][1], val ? h1 : NEG_BIG);
        }
      }
    #pragma unroll
    for (int nt = 0; nt < 8; nt++)
      #pragma unroll
      for (int j = 0; j < 2; j++) {
        mx[nt][j] = fmaxf(mx[nt][j], __shfl_xor_sync(0xffffffffu, mx[nt][j], 4));
        mx[nt][j] = fmaxf(mx[nt][j], __shfl_xor_sync(0xffffffffu, mx[nt][j], 8));
        mx[nt][j] = fmaxf(mx[nt][j], __shfl_xor_sync(0xffffffffu, mx[nt][j], 16));
      }
    if (lane < 4) {
      #pragma unroll
      for (int nt = 0; nt < 8; nt++) {
        sm.pmax[warpM][CB + nt * 8 + qc * 2]     = mx[nt][0];
        sm.pmax[warpM][CB + nt * 8 + qc * 2 + 1] = mx[nt][1];
      }
    }
    __syncthreads();

    // agg = combine warpM pairs per poly
    {
      int p = tid >> 7, cc = tid & 127;
      sm.agg[p][cc] = fmaxf(sm.pmax[2 * p][cc], sm.pmax[2 * p + 1][cc]);
    }
    __syncthreads();

    // aggw = b2 + agg @ W2_bottom (CUDA-core GEMV)
    {
      int p = tid >> 7, e = tid & 127;
      const float* wb = W2 + ((size_t)l * 256 + 128) * 128 + e;
      float a = __ldg(&b2[l * 128 + e]);
      #pragma unroll 8
      for (int dd = 0; dd < 128; dd++) a = fmaf(sm.agg[p][dd], __ldg(&wb[dd * 128]), a);
      sm.aggw[p][e] = a;
    }
    if (l < NL - 1) CP_WAIT1(); else CP_WAIT0();   // buf1 (W2top) ready
    __syncthreads();                                // aggw + A + B visible

    // ---- GEMM2 ----
    #pragma unroll
    for (int a = 0; a < 2; a++)
      #pragma unroll
      for (int b = 0; b < 8; b++)
        #pragma unroll
        for (int e = 0; e < 4; e++) acc[a][b][e] = 0.f;
    run_gemm(acc, uAhi, uAlo, uB1, uB1 + 34816, aoff0, aoff1, boff);

    // ---- epilogue 2: + aggw; split for next layer OR final masked max ----
    if (l < NL - 1) {
      #pragma unroll
      for (int mt = 0; mt < 2; mt++)
        #pragma unroll
        for (int hi = 0; hi < 2; hi++) {
          int row = RB + mt * 16 + qr + hi * 8;
          #pragma unroll
          for (int nt = 0; nt < 8; nt++) {
            int c0 = CB + nt * 8 + qc * 2;
            float v0 = acc[mt][nt][2 * hi]     + sm.aggw[mypoly][c0];
            float v1 = acc[mt][nt][2 * hi + 1] + sm.aggw[mypoly][c0 + 1];
            u32 hp, lp; split2(v0, v1, hp, lp);
            *reinterpret_cast<u32*>(&sm.Ahi[row * AST + c0]) = hp;
            *reinterpret_cast<u32*>(&sm.Alo[row * AST + c0]) = lp;
          }
        }
      __syncthreads();   // A ready for next layer's GEMM1; buf1 free for reuse
    } else {
      #pragma unroll
      for (int nt = 0; nt < 8; nt++) { mx[nt][0] = NEG_BIG; mx[nt][1] = NEG_BIG; }
      #pragma unroll
      for (int mt = 0; mt < 2; mt++)
        #pragma unroll
        for (int hi = 0; hi < 2; hi++) {
          int row = RB + mt * 16 + qr + hi * 8;
          bool val = sm.valid[row] != 0;
          #pragma unroll
          for (int nt = 0; nt < 8; nt++) {
            int c0 = CB + nt * 8 + qc * 2;
            float v0 = acc[mt][nt][2 * hi]     + sm.aggw[mypoly][c0];
            float v1 = acc[mt][nt][2 * hi + 1] + sm.aggw[mypoly][c0 + 1];
            mx[nt][0] = fmaxf(mx[nt][0], val ? v0 : NEG_BIG);
            mx[nt][1] = fmaxf(mx[nt][1], val ? v1 : NEG_BIG);
          }
        }
      #pragma unroll
      for (int nt = 0; nt < 8; nt++)
        #pragma unroll
        for (int j = 0; j < 2; j++) {
          mx[nt][j] = fmaxf(mx[nt][j], __shfl_xor_sync(0xffffffffu, mx[nt][j], 4));
          mx[nt][j] = fmaxf(mx[nt][j], __shfl_xor_sync(0xffffffffu, mx[nt][j], 8));
          mx[nt][j] = fmaxf(mx[nt][j], __shfl_xor_sync(0xffffffffu, mx[nt][j], 16));
        }
      if (lane < 4) {
        #pragma unroll
        for (int nt = 0; nt < 8; nt++) {
          sm.pmax[warpM][CB + nt * 8 + qc * 2]     = mx[nt][0];
          sm.pmax[warpM][CB + nt * 8 + qc * 2 + 1] = mx[nt][1];
        }
      }
      __syncthreads();
      int p = tid >> 7, cc = tid & 127;
      float m = fmaxf(sm.pmax[2 * p][cc], sm.pmax[2 * p + 1][cc]);
      if (!sm.pv[p]) m = 0.f;
      out[(size_t)(g0 + p) * 128 + cc] = m;
    }
  }
}

extern "C" void kernel_launch(void* const* d_in, const int* in_sizes, int n_in,
                              void* d_out, int out_size) {
  const float*         x    = (const float*)d_in[0];
  const unsigned char* mask = (const unsigned char*)d_in[1];
  const float*         W1   = (const float*)d_in[2];
  const float*         b1   = (const float*)d_in[3];
  const float*         lng  = (const float*)d_in[4];
  const float*         lnb  = (const float*)d_in[5];
  const float*         W2   = (const float*)d_in[6];
  const float*         b2   = (const float*)d_in[7];
  float* out = (float*)d_out;

  int smem = (int)sizeof(Sm) + 128;
  (void)cudaFuncSetAttribute(polymma_kernel,
                             cudaFuncAttributeMaxDynamicSharedMemorySize, smem);

  prep_kernel<<<(NL * 2 * 128 * 128 + 255) / 256, 256>>>(W1, W2);
  polymma_kernel<<<1024, 256, smem>>>(x, mask, b1, lng, lnb, W2, b2, out);
}

// round 10
// speedup vs baseline: 2.2062x; 1.3429x over previous
#include <cuda_runtime.h>
#include <cuda_bf16.h>
#include <cstdint>

#define NL 3
#define AST 136                      // padded row stride (bf16 elems)
#define NEG_BIG (-3.402823466e38f)

typedef unsigned int u32;
typedef unsigned short u16;

// Pre-split weight images: [l*2+m][hi=0/lo=1][n*AST + k], bf16, [n][k]
__device__ __align__(16) u16 g_Bimg[NL * 2][2][128 * AST];

__device__ __forceinline__ u32 smaddr(const void* p) {
  u32 a; asm("{ .reg .u64 t; cvta.to.shared.u64 t, %1; cvt.u32.u64 %0, t; }"
             : "=r"(a) : "l"(p));
  return a;
}
__device__ __forceinline__ void ldsm4(u32& r0, u32& r1, u32& r2, u32& r3, u32 a) {
  asm volatile("ldmatrix.sync.aligned.m8n8.x4.shared.b16 {%0,%1,%2,%3}, [%4];"
               : "=r"(r0), "=r"(r1), "=r"(r2), "=r"(r3) : "r"(a));
}
__device__ __forceinline__ void mmab(float* c, const u32* a, u32 b0, u32 b1) {
  asm volatile(
    "mma.sync.aligned.m16n8k16.row.col.f32.bf16.bf16.f32 "
    "{%0,%1,%2,%3}, {%4,%5,%6,%7}, {%8,%9}, {%0,%1,%2,%3};"
    : "+f"(c[0]), "+f"(c[1]), "+f"(c[2]), "+f"(c[3])
    : "r"(a[0]), "r"(a[1]), "r"(a[2]), "r"(a[3]), "r"(b0), "r"(b1));
}
__device__ __forceinline__ void cpa16(u32 dst, const void* src) {
  asm volatile("cp.async.cg.shared.global [%0], [%1], 16;" :: "r"(dst), "l"(src) : "memory");
}
#define CP_COMMIT() asm volatile("cp.async.commit_group;" ::: "memory")
#define CP_WAIT0()  asm volatile("cp.async.wait_group 0;" ::: "memory")

__device__ __forceinline__ void split2(float f0, float f1, u32& hp, u32& lp) {
  __nv_bfloat16 h0 = __float2bfloat16(f0), h1 = __float2bfloat16(f1);
  float l0 = f0 - __bfloat162float(h0), l1 = f1 - __bfloat162float(h1);
  __nv_bfloat16 q0 = __float2bfloat16(l0), q1 = __float2bfloat16(l1);
  hp = (u32)__bfloat16_as_ushort(h0) | ((u32)__bfloat16_as_ushort(h1) << 16);
  lp = (u32)__bfloat16_as_ushort(q0) | ((u32)__bfloat16_as_ushort(q1) << 16);
}

// ---------------- prep: split fp32 weights into bf16 hi/lo [n][k] images ----------------
__global__ void prep_kernel(const float* __restrict__ W1, const float* __restrict__ W2) {
  int id = blockIdx.x * blockDim.x + threadIdx.x;
  if (id >= NL * 2 * 128 * 128) return;
  int n = id & 127, k = (id >> 7) & 127, m = (id >> 14) & 1, l = id >> 15;
  float w = m ? W2[((size_t)l * 256 + k) * 128 + n]
              : W1[((size_t)l * 128 + k) * 128 + n];
  __nv_bfloat16 hi = __float2bfloat16(w);
  __nv_bfloat16 lo = __float2bfloat16(w - __bfloat162float(hi));
  g_Bimg[l * 2 + m][0][n * AST + k] = __bfloat16_as_ushort(hi);
  g_Bimg[l * 2 + m][1][n * AST + k] = __bfloat16_as_ushort(lo);
}

// ---------------- main fused kernel: 1 poly per CTA (M=64), 2 CTAs/SM ----------------
struct Sm {
  u16 Ahi[64 * AST];               // 17408 B
  u16 Alo[64 * AST];
  u16 B[2][128 * AST];             // hi,lo of current weight matrix (69632 B)
  float sred[4][64], qred[4][64];
  float pmax[2][128];
  float agg[128], aggw[128];
  float bias[128], g[128], beta[128];
  unsigned char valid[64];
  int pv;
  u32 det[2];
};

__device__ __forceinline__ void copy_B(u32 dst, const u16* src, int tid) {
  const char* s = reinterpret_cast<const char*>(src);
  #pragma unroll
  for (int i = tid; i < 4352; i += 256) cpa16(dst + i * 16, s + (size_t)i * 16);
}

__global__ void __launch_bounds__(256, 2) polymma_kernel(
    const float* __restrict__ x, const unsigned char* __restrict__ mask,
    const float* __restrict__ b1, const float* __restrict__ lng,
    const float* __restrict__ lnb, const float* __restrict__ W2,
    const float* __restrict__ b2, float* __restrict__ out)
{
  extern __shared__ unsigned char smraw[];
  uintptr_t sp = (reinterpret_cast<uintptr_t>(smraw) + 127) & ~(uintptr_t)127;
  Sm& sm = *reinterpret_cast<Sm*>(sp);

  const int tid = threadIdx.x;
  const int wid = tid >> 5, lane = tid & 31;
  const int warpM = wid & 1, warpN = wid >> 1;   // 2 x 4 warp grid
  const int RB = warpM * 32, CB = warpN * 32;
  const int qr = lane >> 2, qc = lane & 3;
  const int poly = blockIdx.x;

  const u32 uAhi = smaddr(sm.Ahi), uAlo = smaddr(sm.Alo);
  const u32 uBhi = smaddr(sm.B[0]), uBlo = smaddr(sm.B[1]);

  // ldmatrix lane-address offsets
  const int arow = (lane & 7) + ((lane >> 3) & 1) * 8;   // row 0..15
  const u32 acol = (u32)((lane >> 4) * 8);
  u32 aoff[2], boff[2];
  #pragma unroll
  for (int mt = 0; mt < 2; mt++)
    aoff[mt] = (u32)(((RB + mt * 16 + arow) * AST + acol) * 2);
  {
    int nrow = (lane & 7) + (lane >> 4) * 8;
    int kcol = ((lane >> 3) & 1) * 8;
    #pragma unroll
    for (int p = 0; p < 2; p++)
      boff[p] = (u32)(((CB + p * 16 + nrow) * AST + kcol) * 2);
  }

  if (tid == 0) sm.pv = 0;
  if (tid < 2) sm.det[tid] = 0u;
  __syncthreads();

  // ---- mask dtype detection (proven R5/R7) ----
  {
    const u32* mw = reinterpret_cast<const u32*>(mask);
    u32 o123 = 0, o23 = 0;
    for (int j = tid; j < 1024; j += 256) {
      u32 w = mw[j];
      o123 |= (w >> 8);
      o23  |= (w >> 16);
    }
    if (o123) atomicOr(&sm.det[0], o123 & 0xffffffu);
    if (o23)  atomicOr(&sm.det[1], o23 & 0xffffu);
  }
  __syncthreads();
  const int mmode = (sm.det[1] & 0xF0F0u) ? 1 : (sm.det[0] ? 0 : 1);

  if (tid < 64) {
    int midx = poly * 64 + tid;
    unsigned char m;
    if (mmode == 0) m = mask[midx] ? 1 : 0;
    else m = (reinterpret_cast<const u32*>(mask)[midx] != 0u) ? 1 : 0;
    sm.valid[tid] = m;
    if (m) atomicOr(&sm.pv, 1);
  }

  // kick first B copy (layer0 W1 hi+lo, contiguous)
  copy_B(uBhi, &g_Bimg[0][0][0], tid);
  CP_COMMIT();
  __syncthreads();   // pv/valid ready
  if (tid < 64 && !sm.pv) sm.valid[tid] = 1;   // neutralize fully-invalid poly

  // ---- prologue: x -> bf16 hi/lo split in A smem ----
  {
    const float4* xs = reinterpret_cast<const float4*>(x + (size_t)poly * 64 * 128);
    const bool pvok = sm.pv != 0;
    #pragma unroll 4
    for (int i = tid; i < 2048; i += 256) {
      int r = i >> 5, c4 = (i & 31) * 4;
      float4 v = make_float4(0.f, 0.f, 0.f, 0.f);
      if (pvok) v = xs[i];
      u32 h0, l0, h1, l1;
      split2(v.x, v.y, h0, l0);
      split2(v.z, v.w, h1, l1);
      *reinterpret_cast<uint2*>(&sm.Ahi[r * AST + c4]) = make_uint2(h0, h1);
      *reinterpret_cast<uint2*>(&sm.Alo[r * AST + c4]) = make_uint2(l0, l1);
    }
  }

  float acc[2][4][4];

  for (int l = 0; l < NL; l++) {
    if (tid < 128) {
      sm.bias[tid] = b1[l * 128 + tid];
      sm.g[tid]    = lng[l * 128 + tid];
      sm.beta[tid] = lnb[l * 128 + tid];
    }
    CP_WAIT0();
    __syncthreads();         // A + B(W1) + params visible

    // ---- GEMM1: fragment-reuse 3-term split ----
    #pragma unroll
    for (int a = 0; a < 2; a++)
      #pragma unroll
      for (int b = 0; b < 4; b++)
        #pragma unroll
        for (int e = 0; e < 4; e++) acc[a][b][e] = 0.f;
    #pragma unroll
    for (int kt = 0; kt < 8; kt++) {
      u32 ah[2][4], al[2][4], bh[2][4], bl[2][4];
      #pragma unroll
      for (int mt = 0; mt < 2; mt++) {
        ldsm4(ah[mt][0], ah[mt][1], ah[mt][2], ah[mt][3], uAhi + aoff[mt] + kt * 32);
        ldsm4(al[mt][0], al[mt][1], al[mt][2], al[mt][3], uAlo + aoff[mt] + kt * 32);
      }
      #pragma unroll
      for (int p = 0; p < 2; p++) {
        ldsm4(bh[p][0], bh[p][1], bh[p][2], bh[p][3], uBhi + boff[p] + kt * 32);
        ldsm4(bl[p][0], bl[p][1], bl[p][2], bl[p][3], uBlo + boff[p] + kt * 32);
      }
      #pragma unroll
      for (int mt = 0; mt < 2; mt++)
        #pragma unroll
        for (int nt = 0; nt < 4; nt++) {
          int p = nt >> 1, h = (nt & 1) * 2;
          mmab(acc[mt][nt], ah[mt], bh[p][h], bh[p][h + 1]);
          mmab(acc[mt][nt], ah[mt], bl[p][h], bl[p][h + 1]);
          mmab(acc[mt][nt], al[mt], bh[p][h], bh[p][h + 1]);
        }
    }

    // ---- epilogue 1: +bias, LN stats ----
    float s[4] = {0.f, 0.f, 0.f, 0.f}, q[4] = {0.f, 0.f, 0.f, 0.f};
    #pragma unroll
    for (int mt = 0; mt < 2; mt++)
      #pragma unroll
      for (int nt = 0; nt < 4; nt++)
        #pragma unroll
        for (int e = 0; e < 4; e++) {
          int c = CB + nt * 8 + qc * 2 + (e & 1);
          float v = acc[mt][nt][e] + sm.bias[c];
          acc[mt][nt][e] = v;
          int rs = mt * 2 + (e >> 1);
          s[rs] += v; q[rs] += v * v;
        }
    #pragma unroll
    for (int rs = 0; rs < 4; rs++) {
      s[rs] += __shfl_xor_sync(0xffffffffu, s[rs], 1);
      s[rs] += __shfl_xor_sync(0xffffffffu, s[rs], 2);
      q[rs] += __shfl_xor_sync(0xffffffffu, q[rs], 1);
      q[rs] += __shfl_xor_sync(0xffffffffu, q[rs], 2);
    }
    if (qc == 0) {
      #pragma unroll
      for (int rs = 0; rs < 4; rs++) {
        int row = RB + (rs >> 1) * 16 + qr + (rs & 1) * 8;
        sm.sred[warpN][row] = s[rs];
        sm.qred[warpN][row] = q[rs];
      }
    }
    __syncthreads();   // all warps done with GEMM1 A/B reads; sred ready

    // overlap: stage W2top of this layer into B
    copy_B(uBhi, &g_Bimg[l * 2 + 1][0][0], tid);
    CP_COMMIT();

    float mean[4], inv[4];
    #pragma unroll
    for (int rs = 0; rs < 4; rs++) {
      int row = RB + (rs >> 1) * 16 + qr + (rs & 1) * 8;
      float st = sm.sred[0][row] + sm.sred[1][row] + sm.sred[2][row] + sm.sred[3][row];
      float qt = sm.qred[0][row] + sm.qred[1][row] + sm.qred[2][row] + sm.qred[3][row];
      mean[rs] = st * (1.f / 128.f);
      inv[rs]  = rsqrtf(fmaf(qt, 1.f / 128.f, -mean[rs] * mean[rs]) + 1e-5f);
    }

    // LN + ReLU, split-store to A, masked col-max partials
    float mx[4][2];
    #pragma unroll
    for (int nt = 0; nt < 4; nt++) { mx[nt][0] = NEG_BIG; mx[nt][1] = NEG_BIG; }
    #pragma unroll
    for (int mt = 0; mt < 2; mt++)
      #pragma unroll
      for (int hi = 0; hi < 2; hi++) {
        int rs = mt * 2 + hi;
        int row = RB + mt * 16 + qr + hi * 8;
        bool val = sm.valid[row] != 0;
        #pragma unroll
        for (int nt = 0; nt < 4; nt++) {
          int c0 = CB + nt * 8 + qc * 2;
          float v0 = acc[mt][nt][2 * hi], v1 = acc[mt][nt][2 * hi + 1];
          float h0 = fmaxf(fmaf((v0 - mean[rs]) * inv[rs], sm.g[c0],     sm.beta[c0]),     0.f);
          float h1 = fmaxf(fmaf((v1 - mean[rs]) * inv[rs], sm.g[c0 + 1], sm.beta[c0 + 1]), 0.f);
          u32 hp, lp; split2(h0, h1, hp, lp);
          *reinterpret_cast<u32*>(&sm.Ahi[row * AST + c0]) = hp;
          *reinterpret_cast<u32*>(&sm.Alo[row * AST + c0]) = lp;
          mx[nt][0] = fmaxf(mx[nt][0], val ? h0 : NEG_BIG);
          mx[nt][1] = fmaxf(mx[nt][1], val ? h1 : NEG_BIG);
        }
      }
    #pragma unroll
    for (int nt = 0; nt < 4; nt++)
      #pragma unroll
      for (int j = 0; j < 2; j++) {
        mx[nt][j] = fmaxf(mx[nt][j], __shfl_xor_sync(0xffffffffu, mx[nt][j], 4));
        mx[nt][j] = fmaxf(mx[nt][j], __shfl_xor_sync(0xffffffffu, mx[nt][j], 8));
        mx[nt][j] = fmaxf(mx[nt][j], __shfl_xor_sync(0xffffffffu, mx[nt][j], 16));
      }
    if (lane < 4) {
      #pragma unroll
      for (int nt = 0; nt < 4; nt++) {
        sm.pmax[warpM][CB + nt * 8 + qc * 2]     = mx[nt][0];
        sm.pmax[warpM][CB + nt * 8 + qc * 2 + 1] = mx[nt][1];
      }
    }
    __syncthreads();

    if (tid < 128) sm.agg[tid] = fmaxf(sm.pmax[0][tid], sm.pmax[1][tid]);
    __syncthreads();

    // aggw = b2 + agg @ W2_bottom (GEMV)
    if (tid < 128) {
      const float* wb = W2 + ((size_t)l * 256 + 128) * 128 + tid;
      float a = __ldg(&b2[l * 128 + tid]);
      #pragma unroll 8
      for (int dd = 0; dd < 128; dd++) a = fmaf(sm.agg[dd], __ldg(&wb[dd * 128]), a);
      sm.aggw[tid] = a;
    }
    CP_WAIT0();
    __syncthreads();   // B(W2top) + A + aggw visible

    // ---- GEMM2 ----
    #pragma unroll
    for (int a = 0; a < 2; a++)
      #pragma unroll
      for (int b = 0; b < 4; b++)
        #pragma unroll
        for (int e = 0; e < 4; e++) acc[a][b][e] = 0.f;
    #pragma unroll
    for (int kt = 0; kt < 8; kt++) {
      u32 ah[2][4], al[2][4], bh[2][4], bl[2][4];
      #pragma unroll
      for (int mt = 0; mt < 2; mt++) {
        ldsm4(ah[mt][0], ah[mt][1], ah[mt][2], ah[mt][3], uAhi + aoff[mt] + kt * 32);
        ldsm4(al[mt][0], al[mt][1], al[mt][2], al[mt][3], uAlo + aoff[mt] + kt * 32);
      }
      #pragma unroll
      for (int p = 0; p < 2; p++) {
        ldsm4(bh[p][0], bh[p][1], bh[p][2], bh[p][3], uBhi + boff[p] + kt * 32);
        ldsm4(bl[p][0], bl[p][1], bl[p][2], bl[p][3], uBlo + boff[p] + kt * 32);
      }
      #pragma unroll
      for (int mt = 0; mt < 2; mt++)
        #pragma unroll
        for (int nt = 0; nt < 4; nt++) {
          int p = nt >> 1, h = (nt & 1) * 2;
          mmab(acc[mt][nt], ah[mt], bh[p][h], bh[p][h + 1]);
          mmab(acc[mt][nt], ah[mt], bl[p][h], bl[p][h + 1]);
          mmab(acc[mt][nt], al[mt], bh[p][h], bh[p][h + 1]);
        }
    }

    // RACE FIX (R8 bug): warps sharing warpM read the same A rows in GEMM2;
    // epilogue-2 overwrites those rows. Barrier before any A write.
    __syncthreads();

    // ---- epilogue 2: + aggw; next-layer split OR final masked max ----
    if (l < NL - 1) {
      #pragma unroll
      for (int mt = 0; mt < 2; mt++)
        #pragma unroll
        for (int hi = 0; hi < 2; hi++) {
          int row = RB + mt * 16 + qr + hi * 8;
          #pragma unroll
          for (int nt = 0; nt < 4; nt++) {
            int c0 = CB + nt * 8 + qc * 2;
            float v0 = acc[mt][nt][2 * hi]     + sm.aggw[c0];
            float v1 = acc[mt][nt][2 * hi + 1] + sm.aggw[c0 + 1];
            u32 hp, lp; split2(v0, v1, hp, lp);
            *reinterpret_cast<u32*>(&sm.Ahi[row * AST + c0]) = hp;
            *reinterpret_cast<u32*>(&sm.Alo[row * AST + c0]) = lp;
          }
        }
      __syncthreads();   // A ready; B free (all warps finished GEMM2)
      copy_B(uBhi, &g_Bimg[(l + 1) * 2][0][0], tid);
      CP_COMMIT();
    } else {
      #pragma unroll
      for (int nt = 0; nt < 4; nt++) { mx[nt][0] = NEG_BIG; mx[nt][1] = NEG_BIG; }
      #pragma unroll
      for (int mt = 0; mt < 2; mt++)
        #pragma unroll
        for (int hi = 0; hi < 2; hi++) {
          int row = RB + mt * 16 + qr + hi * 8;
          bool val = sm.valid[row] != 0;
          #pragma unroll
          for (int nt = 0; nt < 4; nt++) {
            int c0 = CB + nt * 8 + qc * 2;
            float v0 = acc[mt][nt][2 * hi]     + sm.aggw[c0];
            float v1 = acc[mt][nt][2 * hi + 1] + sm.aggw[c0 + 1];
            mx[nt][0] = fmaxf(mx[nt][0], val ? v0 : NEG_BIG);
            mx[nt][1] = fmaxf(mx[nt][1], val ? v1 : NEG_BIG);
          }
        }
      #pragma unroll
      for (int nt = 0; nt < 4; nt++)
        #pragma unroll
        for (int j = 0; j < 2; j++) {
          mx[nt][j] = fmaxf(mx[nt][j], __shfl_xor_sync(0xffffffffu, mx[nt][j], 4));
          mx[nt][j] = fmaxf(mx[nt][j], __shfl_xor_sync(0xffffffffu, mx[nt][j], 8));
          mx[nt][j] = fmaxf(mx[nt][j], __shfl_xor_sync(0xffffffffu, mx[nt][j], 16));
        }
      if (lane < 4) {
        #pragma unroll
        for (int nt = 0; nt < 4; nt++) {
          sm.pmax[warpM][CB + nt * 8 + qc * 2]     = mx[nt][0];
          sm.pmax[warpM][CB + nt * 8 + qc * 2 + 1] = mx[nt][1];
        }
      }
      __syncthreads();
      if (tid < 128) {
        float m = fmaxf(sm.pmax[0][tid], sm.pmax[1][tid]);
        if (!sm.pv) m = 0.f;
        out[(size_t)poly * 128 + tid] = m;
      }
    }
  }
}

extern "C" void kernel_launch(void* const* d_in, const int* in_sizes, int n_in,
                              void* d_out, int out_size) {
  const float*         x    = (const float*)d_in[0];
  const unsigned char* mask = (const unsigned char*)d_in[1];
  const float*         W1   = (const float*)d_in[2];
  const float*         b1   = (const float*)d_in[3];
  const float*         lng  = (const float*)d_in[4];
  const float*         lnb  = (const float*)d_in[5];
  const float*         W2   = (const float*)d_in[6];
  const float*         b2   = (const float*)d_in[7];
  float* out = (float*)d_out;

  int smem = (int)sizeof(Sm) + 128;
  (void)cudaFuncSetAttribute(polymma_kernel,
                             cudaFuncAttributeMaxDynamicSharedMemorySize, smem);

  prep_kernel<<<(NL * 2 * 128 * 128 + 255) / 256, 256>>>(W1, W2);
  polymma_kernel<<<2048, 256, smem>>>(x, mask, b1, lng, lnb, W2, b2, out);
}

// round 11
// speedup vs baseline: 2.4250x; 1.0992x over previous
#include <cuda_runtime.h>
#include <cuda_bf16.h>
#include <cstdint>

#define NL 3
#define AST 136                      // padded row stride (bf16 elems)
#define NEG_BIG (-3.402823466e38f)

typedef unsigned int u32;
typedef unsigned short u16;

// Pre-split weight images: [l*2+m][hi=0/lo=1][n*AST + k], bf16, [n][k]
__device__ __align__(16) u16 g_Bimg[NL * 2][2][128 * AST];

__device__ __forceinline__ u32 smaddr(const void* p) {
  u32 a; asm("{ .reg .u64 t; cvta.to.shared.u64 t, %1; cvt.u32.u64 %0, t; }"
             : "=r"(a) : "l"(p));
  return a;
}
__device__ __forceinline__ void ldsm4(u32& r0, u32& r1, u32& r2, u32& r3, u32 a) {
  asm volatile("ldmatrix.sync.aligned.m8n8.x4.shared.b16 {%0,%1,%2,%3}, [%4];"
               : "=r"(r0), "=r"(r1), "=r"(r2), "=r"(r3) : "r"(a));
}
__device__ __forceinline__ void mmab(float* c, const u32* a, u32 b0, u32 b1) {
  asm volatile(
    "mma.sync.aligned.m16n8k16.row.col.f32.bf16.bf16.f32 "
    "{%0,%1,%2,%3}, {%4,%5,%6,%7}, {%8,%9}, {%0,%1,%2,%3};"
    : "+f"(c[0]), "+f"(c[1]), "+f"(c[2]), "+f"(c[3])
    : "r"(a[0]), "r"(a[1]), "r"(a[2]), "r"(a[3]), "r"(b0), "r"(b1));
}
__device__ __forceinline__ void cpa16(u32 dst, const void* src) {
  asm volatile("cp.async.cg.shared.global [%0], [%1], 16;" :: "r"(dst), "l"(src) : "memory");
}
#define CP_COMMIT() asm volatile("cp.async.commit_group;" ::: "memory")
#define CP_WAIT0()  asm volatile("cp.async.wait_group 0;" ::: "memory")

// Fast hi/lo bf16 split: packed cvt + bit-unpack (identical rounding to
// __float2bfloat16: round-to-nearest-even).
__device__ __forceinline__ void split2(float f0, float f1, u32& hp, u32& lp) {
  u32 h;
  asm("cvt.rn.bf16x2.f32 %0, %1, %2;" : "=r"(h) : "f"(f1), "f"(f0));
  float h0 = __uint_as_float(h << 16);
  float h1 = __uint_as_float(h & 0xffff0000u);
  float l0 = f0 - h0, l1 = f1 - h1;
  asm("cvt.rn.bf16x2.f32 %0, %1, %2;" : "=r"(lp) : "f"(l1), "f"(l0));
  hp = h;
}

// ---------------- prep: split fp32 weights into bf16 hi/lo [n][k] images ----------------
__global__ void prep_kernel(const float* __restrict__ W1, const float* __restrict__ W2) {
  int id = blockIdx.x * blockDim.x + threadIdx.x;
  if (id >= NL * 2 * 128 * 128) return;
  int n = id & 127, k = (id >> 7) & 127, m = (id >> 14) & 1, l = id >> 15;
  float w = m ? W2[((size_t)l * 256 + k) * 128 + n]
              : W1[((size_t)l * 128 + k) * 128 + n];
  __nv_bfloat16 hi = __float2bfloat16(w);
  __nv_bfloat16 lo = __float2bfloat16(w - __bfloat162float(hi));
  g_Bimg[l * 2 + m][0][n * AST + k] = __bfloat16_as_ushort(hi);
  g_Bimg[l * 2 + m][1][n * AST + k] = __bfloat16_as_ushort(lo);
}

// ---------------- main fused kernel: 1 poly per CTA (M=64), 2 CTAs/SM ----------------
struct Sm {
  u16 Ahi[64 * AST];               // 17408 B
  u16 Alo[64 * AST];
  u16 B[2][128 * AST];             // hi,lo of current weight matrix (69632 B)
  float sred[4][64], qred[4][64];
  float pmax[2][128];
  float gpart[2][128];             // GEMV partials (incl. b2 in gpart[0])
  float bias[128], g[128], beta[128];
  unsigned char valid[64];
  int pv;
  u32 det[2];
};

__device__ __forceinline__ void copy_B(u32 dst, const u16* src, int tid) {
  const char* s = reinterpret_cast<const char*>(src);
  #pragma unroll
  for (int i = tid; i < 4352; i += 256) cpa16(dst + i * 16, s + (size_t)i * 16);
}

__global__ void __launch_bounds__(256, 2) polymma_kernel(
    const float* __restrict__ x, const unsigned char* __restrict__ mask,
    const float* __restrict__ b1, const float* __restrict__ lng,
    const float* __restrict__ lnb, const float* __restrict__ W2,
    const float* __restrict__ b2, float* __restrict__ out)
{
  extern __shared__ unsigned char smraw[];
  uintptr_t sp = (reinterpret_cast<uintptr_t>(smraw) + 127) & ~(uintptr_t)127;
  Sm& sm = *reinterpret_cast<Sm*>(sp);

  const int tid = threadIdx.x;
  const int wid = tid >> 5, lane = tid & 31;
  const int warpM = wid & 1, warpN = wid >> 1;   // 2 x 4 warp grid
  const int RB = warpM * 32, CB = warpN * 32;
  const int qr = lane >> 2, qc = lane & 3;
  const int poly = blockIdx.x;

  const u32 uAhi = smaddr(sm.Ahi), uAlo = smaddr(sm.Alo);
  const u32 uBhi = smaddr(sm.B[0]), uBlo = smaddr(sm.B[1]);

  // ldmatrix lane-address offsets
  const int arow = (lane & 7) + ((lane >> 3) & 1) * 8;   // row 0..15
  const u32 acol = (u32)((lane >> 4) * 8);
  u32 aoff[2], boff[2];
  #pragma unroll
  for (int mt = 0; mt < 2; mt++)
    aoff[mt] = (u32)(((RB + mt * 16 + arow) * AST + acol) * 2);
  {
    int nrow = (lane & 7) + (lane >> 4) * 8;
    int kcol = ((lane >> 3) & 1) * 8;
    #pragma unroll
    for (int p = 0; p < 2; p++)
      boff[p] = (u32)(((CB + p * 16 + nrow) * AST + kcol) * 2);
  }

  if (tid == 0) sm.pv = 0;
  if (tid < 2) sm.det[tid] = 0u;
  __syncthreads();

  // ---- mask dtype detection (proven R5/R7/R10) ----
  {
    const u32* mw = reinterpret_cast<const u32*>(mask);
    u32 o123 = 0, o23 = 0;
    for (int j = tid; j < 1024; j += 256) {
      u32 w = mw[j];
      o123 |= (w >> 8);
      o23  |= (w >> 16);
    }
    if (o123) atomicOr(&sm.det[0], o123 & 0xffffffu);
    if (o23)  atomicOr(&sm.det[1], o23 & 0xffffu);
  }
  __syncthreads();
  const int mmode = (sm.det[1] & 0xF0F0u) ? 1 : (sm.det[0] ? 0 : 1);

  if (tid < 64) {
    int midx = poly * 64 + tid;
    unsigned char m;
    if (mmode == 0) m = mask[midx] ? 1 : 0;
    else m = (reinterpret_cast<const u32*>(mask)[midx] != 0u) ? 1 : 0;
    sm.valid[tid] = m;
    if (m) atomicOr(&sm.pv, 1);
  }

  // kick first B copy (layer0 W1 hi+lo, contiguous)
  copy_B(uBhi, &g_Bimg[0][0][0], tid);
  CP_COMMIT();
  __syncthreads();   // pv/valid ready
  if (tid < 64 && !sm.pv) sm.valid[tid] = 1;   // neutralize fully-invalid poly

  // ---- prologue: x -> bf16 hi/lo split in A smem ----
  {
    const float4* xs = reinterpret_cast<const float4*>(x + (size_t)poly * 64 * 128);
    const bool pvok = sm.pv != 0;
    #pragma unroll 4
    for (int i = tid; i < 2048; i += 256) {
      int r = i >> 5, c4 = (i & 31) * 4;
      float4 v = make_float4(0.f, 0.f, 0.f, 0.f);
      if (pvok) v = xs[i];
      u32 h0, l0, h1, l1;
      split2(v.x, v.y, h0, l0);
      split2(v.z, v.w, h1, l1);
      *reinterpret_cast<uint2*>(&sm.Ahi[r * AST + c4]) = make_uint2(h0, h1);
      *reinterpret_cast<uint2*>(&sm.Alo[r * AST + c4]) = make_uint2(l0, l1);
    }
  }

  float acc[2][4][4];
  float cinit[8];

  for (int l = 0; l < NL; l++) {
    if (tid < 128) {
      sm.bias[tid] = b1[l * 128 + tid];
      sm.g[tid]    = lng[l * 128 + tid];
      sm.beta[tid] = lnb[l * 128 + tid];
    }
    CP_WAIT0();
    __syncthreads();         // A + B(W1) + params visible

    // ---- GEMM1: acc init = bias, fragment-reuse 3-term split ----
    #pragma unroll
    for (int nt = 0; nt < 4; nt++) {
      cinit[nt * 2]     = sm.bias[CB + nt * 8 + qc * 2];
      cinit[nt * 2 + 1] = sm.bias[CB + nt * 8 + qc * 2 + 1];
    }
    #pragma unroll
    for (int a = 0; a < 2; a++)
      #pragma unroll
      for (int b = 0; b < 4; b++)
        #pragma unroll
        for (int e = 0; e < 4; e++) acc[a][b][e] = cinit[b * 2 + (e & 1)];
    #pragma unroll
    for (int kt = 0; kt < 8; kt++) {
      u32 ah[2][4], al[2][4], bh[2][4], bl[2][4];
      #pragma unroll
      for (int mt = 0; mt < 2; mt++) {
        ldsm4(ah[mt][0], ah[mt][1], ah[mt][2], ah[mt][3], uAhi + aoff[mt] + kt * 32);
        ldsm4(al[mt][0], al[mt][1], al[mt][2], al[mt][3], uAlo + aoff[mt] + kt * 32);
      }
      #pragma unroll
      for (int p = 0; p < 2; p++) {
        ldsm4(bh[p][0], bh[p][1], bh[p][2], bh[p][3], uBhi + boff[p] + kt * 32);
        ldsm4(bl[p][0], bl[p][1], bl[p][2], bl[p][3], uBlo + boff[p] + kt * 32);
      }
      #pragma unroll
      for (int mt = 0; mt < 2; mt++)
        #pragma unroll
        for (int nt = 0; nt < 4; nt++) {
          int p = nt >> 1, h = (nt & 1) * 2;
          mmab(acc[mt][nt], ah[mt], bh[p][h], bh[p][h + 1]);
          mmab(acc[mt][nt], ah[mt], bl[p][h], bl[p][h + 1]);
          mmab(acc[mt][nt], al[mt], bh[p][h], bh[p][h + 1]);
        }
    }

    // ---- epilogue 1: LN stats (bias already in acc) ----
    float s[4] = {0.f, 0.f, 0.f, 0.f}, q[4] = {0.f, 0.f, 0.f, 0.f};
    #pragma unroll
    for (int mt = 0; mt < 2; mt++)
      #pragma unroll
      for (int nt = 0; nt < 4; nt++)
        #pragma unroll
        for (int e = 0; e < 4; e++) {
          float v = acc[mt][nt][e];
          int rs = mt * 2 + (e >> 1);
          s[rs] += v; q[rs] += v * v;
        }
    #pragma unroll
    for (int rs = 0; rs < 4; rs++) {
      s[rs] += __shfl_xor_sync(0xffffffffu, s[rs], 1);
      s[rs] += __shfl_xor_sync(0xffffffffu, s[rs], 2);
      q[rs] += __shfl_xor_sync(0xffffffffu, q[rs], 1);
      q[rs] += __shfl_xor_sync(0xffffffffu, q[rs], 2);
    }
    if (qc == 0) {
      #pragma unroll
      for (int rs = 0; rs < 4; rs++) {
        int row = RB + (rs >> 1) * 16 + qr + (rs & 1) * 8;
        sm.sred[warpN][row] = s[rs];
        sm.qred[warpN][row] = q[rs];
      }
    }
    __syncthreads();   // all warps done with GEMM1 A/B reads; sred ready

    // overlap: stage W2top of this layer into B
    copy_B(uBhi, &g_Bimg[l * 2 + 1][0][0], tid);
    CP_COMMIT();

    float mean[4], inv[4];
    #pragma unroll
    for (int rs = 0; rs < 4; rs++) {
      int row = RB + (rs >> 1) * 16 + qr + (rs & 1) * 8;
      float st = sm.sred[0][row] + sm.sred[1][row] + sm.sred[2][row] + sm.sred[3][row];
      float qt = sm.qred[0][row] + sm.qred[1][row] + sm.qred[2][row] + sm.qred[3][row];
      mean[rs] = st * (1.f / 128.f);
      inv[rs]  = rsqrtf(fmaf(qt, 1.f / 128.f, -mean[rs] * mean[rs]) + 1e-5f);
    }

    // LN + ReLU, split-store to A, masked col-max partials
    float mx[4][2];
    #pragma unroll
    for (int nt = 0; nt < 4; nt++) { mx[nt][0] = NEG_BIG; mx[nt][1] = NEG_BIG; }
    #pragma unroll
    for (int mt = 0; mt < 2; mt++)
      #pragma unroll
      for (int hi = 0; hi < 2; hi++) {
        int rs = mt * 2 + hi;
        int row = RB + mt * 16 + qr + hi * 8;
        bool val = sm.valid[row] != 0;
        #pragma unroll
        for (int nt = 0; nt < 4; nt++) {
          int c0 = CB + nt * 8 + qc * 2;
          float v0 = acc[mt][nt][2 * hi], v1 = acc[mt][nt][2 * hi + 1];
          float h0 = fmaxf(fmaf((v0 - mean[rs]) * inv[rs], sm.g[c0],     sm.beta[c0]),     0.f);
          float h1 = fmaxf(fmaf((v1 - mean[rs]) * inv[rs], sm.g[c0 + 1], sm.beta[c0 + 1]), 0.f);
          u32 hp, lp; split2(h0, h1, hp, lp);
          *reinterpret_cast<u32*>(&sm.Ahi[row * AST + c0]) = hp;
          *reinterpret_cast<u32*>(&sm.Alo[row * AST + c0]) = lp;
          mx[nt][0] = fmaxf(mx[nt][0], val ? h0 : NEG_BIG);
          mx[nt][1] = fmaxf(mx[nt][1], val ? h1 : NEG_BIG);
        }
      }
    #pragma unroll
    for (int nt = 0; nt < 4; nt++)
      #pragma unroll
      for (int j = 0; j < 2; j++) {
        mx[nt][j] = fmaxf(mx[nt][j], __shfl_xor_sync(0xffffffffu, mx[nt][j], 4));
        mx[nt][j] = fmaxf(mx[nt][j], __shfl_xor_sync(0xffffffffu, mx[nt][j], 8));
        mx[nt][j] = fmaxf(mx[nt][j], __shfl_xor_sync(0xffffffffu, mx[nt][j], 16));
      }
    if (lane < 4) {
      #pragma unroll
      for (int nt = 0; nt < 4; nt++) {
        sm.pmax[warpM][CB + nt * 8 + qc * 2]     = mx[nt][0];
        sm.pmax[warpM][CB + nt * 8 + qc * 2 + 1] = mx[nt][1];
      }
    }
    __syncthreads();   // pmax + A(next input for GEMM2) visible

    // ---- GEMV partials: aggw = b2 + max(pmax0,pmax1) @ W2_bottom, 256 threads ----
    {
      int e = tid & 127, h = tid >> 7;
      const float* wb = W2 + ((size_t)l * 256 + 128) * 128 + e;
      float a = h ? 0.f : __ldg(&b2[l * 128 + e]);
      int d0 = h * 64;
      #pragma unroll 8
      for (int dd = d0; dd < d0 + 64; dd++)
        a = fmaf(fmaxf(sm.pmax[0][dd], sm.pmax[1][dd]), __ldg(&wb[(size_t)dd * 128]), a);
      sm.gpart[h][e] = a;
    }
    CP_WAIT0();
    __syncthreads();   // B(W2top) + gpart visible

    // ---- GEMM2: acc init = aggw (gpart0+gpart1) ----
    #pragma unroll
    for (int nt = 0; nt < 4; nt++) {
      int c0 = CB + nt * 8 + qc * 2;
      cinit[nt * 2]     = sm.gpart[0][c0]     + sm.gpart[1][c0];
      cinit[nt * 2 + 1] = sm.gpart[0][c0 + 1] + sm.gpart[1][c0 + 1];
    }
    #pragma unroll
    for (int a = 0; a < 2; a++)
      #pragma unroll
      for (int b = 0; b < 4; b++)
        #pragma unroll
        for (int e = 0; e < 4; e++) acc[a][b][e] = cinit[b * 2 + (e & 1)];
    #pragma unroll
    for (int kt = 0; kt < 8; kt++) {
      u32 ah[2][4], al[2][4], bh[2][4], bl[2][4];
      #pragma unroll
      for (int mt = 0; mt < 2; mt++) {
        ldsm4(ah[mt][0], ah[mt][1], ah[mt][2], ah[mt][3], uAhi + aoff[mt] + kt * 32);
        ldsm4(al[mt][0], al[mt][1], al[mt][2], al[mt][3], uAlo + aoff[mt] + kt * 32);
      }
      #pragma unroll
      for (int p = 0; p < 2; p++) {
        ldsm4(bh[p][0], bh[p][1], bh[p][2], bh[p][3], uBhi + boff[p] + kt * 32);
        ldsm4(bl[p][0], bl[p][1], bl[p][2], bl[p][3], uBlo + boff[p] + kt * 32);
      }
      #pragma unroll
      for (int mt = 0; mt < 2; mt++)
        #pragma unroll
        for (int nt = 0; nt < 4; nt++) {
          int p = nt >> 1, h = (nt & 1) * 2;
          mmab(acc[mt][nt], ah[mt], bh[p][h], bh[p][h + 1]);
          mmab(acc[mt][nt], ah[mt], bl[p][h], bl[p][h + 1]);
          mmab(acc[mt][nt], al[mt], bh[p][h], bh[p][h + 1]);
        }
    }

    // RACE FIX: warps sharing warpM read the same A rows in GEMM2;
    // epilogue-2 overwrites those rows. Barrier before any A write.
    __syncthreads();

    // ---- epilogue 2: next-layer split OR final masked max (aggw already in acc) ----
    if (l < NL - 1) {
      #pragma unroll
      for (int mt = 0; mt < 2; mt++)
        #pragma unroll
        for (int hi = 0; hi < 2; hi++) {
          int row = RB + mt * 16 + qr + hi * 8;
          #pragma unroll
          for (int nt = 0; nt < 4; nt++) {
            int c0 = CB + nt * 8 + qc * 2;
            u32 hp, lp; split2(acc[mt][nt][2 * hi], acc[mt][nt][2 * hi + 1], hp, lp);
            *reinterpret_cast<u32*>(&sm.Ahi[row * AST + c0]) = hp;
            *reinterpret_cast<u32*>(&sm.Alo[row * AST + c0]) = lp;
          }
        }
      __syncthreads();   // A ready; B free (all warps finished GEMM2)
      copy_B(uBhi, &g_Bimg[(l + 1) * 2][0][0], tid);
      CP_COMMIT();
    } else {
      float mx2[4][2];
      #pragma unroll
      for (int nt = 0; nt < 4; nt++) { mx2[nt][0] = NEG_BIG; mx2[nt][1] = NEG_BIG; }
      #pragma unroll
      for (int mt = 0; mt < 2; mt++)
        #pragma unroll
        for (int hi = 0; hi < 2; hi++) {
          int row = RB + mt * 16 + qr + hi * 8;
          bool val = sm.valid[row] != 0;
          #pragma unroll
          for (int nt = 0; nt < 4; nt++) {
            mx2[nt][0] = fmaxf(mx2[nt][0], val ? acc[mt][nt][2 * hi]     : NEG_BIG);
            mx2[nt][1] = fmaxf(mx2[nt][1], val ? acc[mt][nt][2 * hi + 1] : NEG_BIG);
          }
        }
      #pragma unroll
      for (int nt = 0; nt < 4; nt++)
        #pragma unroll
        for (int j = 0; j < 2; j++) {
          mx2[nt][j] = fmaxf(mx2[nt][j], __shfl_xor_sync(0xffffffffu, mx2[nt][j], 4));
          mx2[nt][j] = fmaxf(mx2[nt][j], __shfl_xor_sync(0xffffffffu, mx2[nt][j], 8));
          mx2[nt][j] = fmaxf(mx2[nt][j], __shfl_xor_sync(0xffffffffu, mx2[nt][j], 16));
        }
      if (lane < 4) {
        #pragma unroll
        for (int nt = 0; nt < 4; nt++) {
          sm.pmax[warpM][CB + nt * 8 + qc * 2]     = mx2[nt][0];
          sm.pmax[warpM][CB + nt * 8 + qc * 2 + 1] = mx2[nt][1];
        }
      }
      __syncthreads();
      if (tid < 128) {
        float m = fmaxf(sm.pmax[0][tid], sm.pmax[1][tid]);
        if (!sm.pv) m = 0.f;
        out[(size_t)poly * 128 + tid] = m;
      }
    }
  }
}

extern "C" void kernel_launch(void* const* d_in, const int* in_sizes, int n_in,
                              void* d_out, int out_size) {
  const float*         x    = (const float*)d_in[0];
  const unsigned char* mask = (const unsigned char*)d_in[1];
  const float*         W1   = (const float*)d_in[2];
  const float*         b1   = (const float*)d_in[3];
  const float*         lng  = (const float*)d_in[4];
  const float*         lnb  = (const float*)d_in[5];
  const float*         W2   = (const float*)d_in[6];
  const float*         b2   = (const float*)d_in[7];
  float* out = (float*)d_out;

  int smem = (int)sizeof(Sm) + 128;
  (void)cudaFuncSetAttribute(polymma_kernel,
                             cudaFuncAttributeMaxDynamicSharedMemorySize, smem);

  prep_kernel<<<(NL * 2 * 128 * 128 + 255) / 256, 256>>>(W1, W2);
  polymma_kernel<<<2048, 256, smem>>>(x, mask, b1, lng, lnb, W2, b2, out);
}

// round 12
// speedup vs baseline: 2.4819x; 1.0235x over previous
#include <cuda_runtime.h>
#include <cuda_bf16.h>
#include <cstdint>

#define NL 3
#define AST 136                      // padded row stride (bf16 elems)
#define NEG_BIG (-3.402823466e38f)

typedef unsigned int u32;
typedef unsigned short u16;

// Pre-split weight images: [l*2+m][hi=0/lo=1][n*AST + k], bf16, [n][k]
__device__ __align__(16) u16 g_Bimg[NL * 2][2][128 * AST];

__device__ __forceinline__ u32 smaddr(const void* p) {
  u32 a; asm("{ .reg .u64 t; cvta.to.shared.u64 t, %1; cvt.u32.u64 %0, t; }"
             : "=r"(a) : "l"(p));
  return a;
}
__device__ __forceinline__ void ldsm4(u32& r0, u32& r1, u32& r2, u32& r3, u32 a) {
  asm volatile("ldmatrix.sync.aligned.m8n8.x4.shared.b16 {%0,%1,%2,%3}, [%4];"
               : "=r"(r0), "=r"(r1), "=r"(r2), "=r"(r3) : "r"(a));
}
__device__ __forceinline__ void mmab(float* c, const u32* a, u32 b0, u32 b1) {
  asm volatile(
    "mma.sync.aligned.m16n8k16.row.col.f32.bf16.bf16.f32 "
    "{%0,%1,%2,%3}, {%4,%5,%6,%7}, {%8,%9}, {%0,%1,%2,%3};"
    : "+f"(c[0]), "+f"(c[1]), "+f"(c[2]), "+f"(c[3])
    : "r"(a[0]), "r"(a[1]), "r"(a[2]), "r"(a[3]), "r"(b0), "r"(b1));
}
__device__ __forceinline__ void cpa16(u32 dst, const void* src) {
  asm volatile("cp.async.cg.shared.global [%0], [%1], 16;" :: "r"(dst), "l"(src) : "memory");
}
#define CP_COMMIT() asm volatile("cp.async.commit_group;" ::: "memory")
#define CP_WAIT0()  asm volatile("cp.async.wait_group 0;" ::: "memory")

// Fast hi/lo bf16 split: packed cvt + bit-unpack (identical rounding to
// __float2bfloat16: round-to-nearest-even).
__device__ __forceinline__ void split2(float f0, float f1, u32& hp, u32& lp) {
  u32 h;
  asm("cvt.rn.bf16x2.f32 %0, %1, %2;" : "=r"(h) : "f"(f1), "f"(f0));
  float h0 = __uint_as_float(h << 16);
  float h1 = __uint_as_float(h & 0xffff0000u);
  float l0 = f0 - h0, l1 = f1 - h1;
  asm("cvt.rn.bf16x2.f32 %0, %1, %2;" : "=r"(lp) : "f"(l1), "f"(l0));
  hp = h;
}

// ---------------- prep: split fp32 weights into bf16 hi/lo [n][k] images ----------------
__global__ void prep_kernel(const float* __restrict__ W1, const float* __restrict__ W2) {
  int id = blockIdx.x * blockDim.x + threadIdx.x;
  if (id >= NL * 2 * 128 * 128) return;
  int n = id & 127, k = (id >> 7) & 127, m = (id >> 14) & 1, l = id >> 15;
  float w = m ? W2[((size_t)l * 256 + k) * 128 + n]
              : W1[((size_t)l * 128 + k) * 128 + n];
  __nv_bfloat16 hi = __float2bfloat16(w);
  __nv_bfloat16 lo = __float2bfloat16(w - __bfloat162float(hi));
  g_Bimg[l * 2 + m][0][n * AST + k] = __bfloat16_as_ushort(hi);
  g_Bimg[l * 2 + m][1][n * AST + k] = __bfloat16_as_ushort(lo);
}

// ---------------- main fused kernel: 1 poly per CTA (M=64), 2 CTAs/SM ----------------
struct Sm {
  u16 Ahi[64 * AST];               // 17408 B
  u16 Alo[64 * AST];
  u16 B[2][128 * AST];             // hi,lo of current weight matrix (69632 B)
  float sred[4][64], qred[4][64];
  float pmax[2][128];
  float gpart[2][128];             // GEMV partials (incl. b2 in gpart[0])
  float bias[128], g[128], beta[128];
  unsigned char valid[64];
  int pv;
  u32 det[2];
};

__device__ __forceinline__ void copy_B(u32 dst, const u16* src, int tid) {
  const char* s = reinterpret_cast<const char*>(src);
  #pragma unroll
  for (int i = tid; i < 4352; i += 256) cpa16(dst + i * 16, s + (size_t)i * 16);
}

__global__ void __launch_bounds__(256, 2) polymma_kernel(
    const float* __restrict__ x, const unsigned char* __restrict__ mask,
    const float* __restrict__ b1, const float* __restrict__ lng,
    const float* __restrict__ lnb, const float* __restrict__ W2,
    const float* __restrict__ b2, float* __restrict__ out)
{
  extern __shared__ unsigned char smraw[];
  uintptr_t sp = (reinterpret_cast<uintptr_t>(smraw) + 127) & ~(uintptr_t)127;
  Sm& sm = *reinterpret_cast<Sm*>(sp);

  const int tid = threadIdx.x;
  const int wid = tid >> 5, lane = tid & 31;
  const int warpM = wid & 1, warpN = wid >> 1;   // 2 x 4 warp grid
  const int RB = warpM * 32, CB = warpN * 32;
  const int qr = lane >> 2, qc = lane & 3;
  const int poly = blockIdx.x;

  // ---- anti-phase stagger: wave-1 second-slot CTAs (bid 148..295 share an SM
  // with bid-148). Delay them ~2us once so the two co-resident CTAs run
  // GEMM/epilogue phases anti-phased; the offset propagates through later
  // waves because staggered CTAs also finish staggered.
  if (poly >= 148 && poly < 296) __nanosleep(2000);

  const u32 uAhi = smaddr(sm.Ahi), uAlo = smaddr(sm.Alo);
  const u32 uBhi = smaddr(sm.B[0]), uBlo = smaddr(sm.B[1]);

  // ldmatrix lane-address offsets
  const int arow = (lane & 7) + ((lane >> 3) & 1) * 8;   // row 0..15
  const u32 acol = (u32)((lane >> 4) * 8);
  u32 aoff[2], boff[2];
  #pragma unroll
  for (int mt = 0; mt < 2; mt++)
    aoff[mt] = (u32)(((RB + mt * 16 + arow) * AST + acol) * 2);
  {
    int nrow = (lane & 7) + (lane >> 4) * 8;
    int kcol = ((lane >> 3) & 1) * 8;
    #pragma unroll
    for (int p = 0; p < 2; p++)
      boff[p] = (u32)(((CB + p * 16 + nrow) * AST + kcol) * 2);
  }

  if (tid == 0) sm.pv = 0;
  if (tid < 2) sm.det[tid] = 0u;
  __syncthreads();

  // ---- mask dtype detection (proven R5/R7/R10) ----
  {
    const u32* mw = reinterpret_cast<const u32*>(mask);
    u32 o123 = 0, o23 = 0;
    for (int j = tid; j < 1024; j += 256) {
      u32 w = mw[j];
      o123 |= (w >> 8);
      o23  |= (w >> 16);
    }
    if (o123) atomicOr(&sm.det[0], o123 & 0xffffffu);
    if (o23)  atomicOr(&sm.det[1], o23 & 0xffffu);
  }
  __syncthreads();
  const int mmode = (sm.det[1] & 0xF0F0u) ? 1 : (sm.det[0] ? 0 : 1);

  if (tid < 64) {
    int midx = poly * 64 + tid;
    unsigned char m;
    if (mmode == 0) m = mask[midx] ? 1 : 0;
    else m = (reinterpret_cast<const u32*>(mask)[midx] != 0u) ? 1 : 0;
    sm.valid[tid] = m;
    if (m) atomicOr(&sm.pv, 1);
  }

  // kick first B copy (layer0 W1 hi+lo, contiguous)
  copy_B(uBhi, &g_Bimg[0][0][0], tid);
  CP_COMMIT();
  __syncthreads();   // pv/valid ready
  if (tid < 64 && !sm.pv) sm.valid[tid] = 1;   // neutralize fully-invalid poly

  // ---- prologue: x -> bf16 hi/lo split in A smem ----
  {
    const float4* xs = reinterpret_cast<const float4*>(x + (size_t)poly * 64 * 128);
    const bool pvok = sm.pv != 0;
    #pragma unroll 4
    for (int i = tid; i < 2048; i += 256) {
      int r = i >> 5, c4 = (i & 31) * 4;
      float4 v = make_float4(0.f, 0.f, 0.f, 0.f);
      if (pvok) v = xs[i];
      u32 h0, l0, h1, l1;
      split2(v.x, v.y, h0, l0);
      split2(v.z, v.w, h1, l1);
      *reinterpret_cast<uint2*>(&sm.Ahi[r * AST + c4]) = make_uint2(h0, h1);
      *reinterpret_cast<uint2*>(&sm.Alo[r * AST + c4]) = make_uint2(l0, l1);
    }
  }

  float acc[2][4][4];
  float cinit[8];

  for (int l = 0; l < NL; l++) {
    if (tid < 128) {
      sm.bias[tid] = b1[l * 128 + tid];
      sm.g[tid]    = lng[l * 128 + tid];
      sm.beta[tid] = lnb[l * 128 + tid];
    }
    CP_WAIT0();
    __syncthreads();         // A + B(W1) + params visible

    // ---- GEMM1: acc init = bias, fragment-reuse 3-term split ----
    #pragma unroll
    for (int nt = 0; nt < 4; nt++) {
      cinit[nt * 2]     = sm.bias[CB + nt * 8 + qc * 2];
      cinit[nt * 2 + 1] = sm.bias[CB + nt * 8 + qc * 2 + 1];
    }
    #pragma unroll
    for (int a = 0; a < 2; a++)
      #pragma unroll
      for (int b = 0; b < 4; b++)
        #pragma unroll
        for (int e = 0; e < 4; e++) acc[a][b][e] = cinit[b * 2 + (e & 1)];
    #pragma unroll
    for (int kt = 0; kt < 8; kt++) {
      u32 ah[2][4], al[2][4], bh[2][4], bl[2][4];
      #pragma unroll
      for (int mt = 0; mt < 2; mt++) {
        ldsm4(ah[mt][0], ah[mt][1], ah[mt][2], ah[mt][3], uAhi + aoff[mt] + kt * 32);
        ldsm4(al[mt][0], al[mt][1], al[mt][2], al[mt][3], uAlo + aoff[mt] + kt * 32);
      }
      #pragma unroll
      for (int p = 0; p < 2; p++) {
        ldsm4(bh[p][0], bh[p][1], bh[p][2], bh[p][3], uBhi + boff[p] + kt * 32);
        ldsm4(bl[p][0], bl[p][1], bl[p][2], bl[p][3], uBlo + boff[p] + kt * 32);
      }
      #pragma unroll
      for (int mt = 0; mt < 2; mt++)
        #pragma unroll
        for (int nt = 0; nt < 4; nt++) {
          int p = nt >> 1, h = (nt & 1) * 2;
          mmab(acc[mt][nt], ah[mt], bh[p][h], bh[p][h + 1]);
          mmab(acc[mt][nt], ah[mt], bl[p][h], bl[p][h + 1]);
          mmab(acc[mt][nt], al[mt], bh[p][h], bh[p][h + 1]);
        }
    }

    // ---- epilogue 1: LN stats (bias already in acc) ----
    float s[4] = {0.f, 0.f, 0.f, 0.f}, q[4] = {0.f, 0.f, 0.f, 0.f};
    #pragma unroll
    for (int mt = 0; mt < 2; mt++)
      #pragma unroll
      for (int nt = 0; nt < 4; nt++)
        #pragma unroll
        for (int e = 0; e < 4; e++) {
          float v = acc[mt][nt][e];
          int rs = mt * 2 + (e >> 1);
          s[rs] += v; q[rs] += v * v;
        }
    #pragma unroll
    for (int rs = 0; rs < 4; rs++) {
      s[rs] += __shfl_xor_sync(0xffffffffu, s[rs], 1);
      s[rs] += __shfl_xor_sync(0xffffffffu, s[rs], 2);
      q[rs] += __shfl_xor_sync(0xffffffffu, q[rs], 1);
      q[rs] += __shfl_xor_sync(0xffffffffu, q[rs], 2);
    }
    if (qc == 0) {
      #pragma unroll
      for (int rs = 0; rs < 4; rs++) {
        int row = RB + (rs >> 1) * 16 + qr + (rs & 1) * 8;
        sm.sred[warpN][row] = s[rs];
        sm.qred[warpN][row] = q[rs];
      }
    }
    __syncthreads();   // all warps done with GEMM1 A/B reads; sred ready

    // overlap: stage W2top of this layer into B
    copy_B(uBhi, &g_Bimg[l * 2 + 1][0][0], tid);
    CP_COMMIT();

    float mean[4], inv[4];
    #pragma unroll
    for (int rs = 0; rs < 4; rs++) {
      int row = RB + (rs >> 1) * 16 + qr + (rs & 1) * 8;
      float st = sm.sred[0][row] + sm.sred[1][row] + sm.sred[2][row] + sm.sred[3][row];
      float qt = sm.qred[0][row] + sm.qred[1][row] + sm.qred[2][row] + sm.qred[3][row];
      mean[rs] = st * (1.f / 128.f);
      inv[rs]  = rsqrtf(fmaf(qt, 1.f / 128.f, -mean[rs] * mean[rs]) + 1e-5f);
    }

    // LN + ReLU, split-store to A, masked col-max partials
    float mx[4][2];
    #pragma unroll
    for (int nt = 0; nt < 4; nt++) { mx[nt][0] = NEG_BIG; mx[nt][1] = NEG_BIG; }
    #pragma unroll
    for (int mt = 0; mt < 2; mt++)
      #pragma unroll
      for (int hi = 0; hi < 2; hi++) {
        int rs = mt * 2 + hi;
        int row = RB + mt * 16 + qr + hi * 8;
        bool val = sm.valid[row] != 0;
        #pragma unroll
        for (int nt = 0; nt < 4; nt++) {
          int c0 = CB + nt * 8 + qc * 2;
          float v0 = acc[mt][nt][2 * hi], v1 = acc[mt][nt][2 * hi + 1];
          float h0 = fmaxf(fmaf((v0 - mean[rs]) * inv[rs], sm.g[c0],     sm.beta[c0]),     0.f);
          float h1 = fmaxf(fmaf((v1 - mean[rs]) * inv[rs], sm.g[c0 + 1], sm.beta[c0 + 1]), 0.f);
          u32 hp, lp; split2(h0, h1, hp, lp);
          *reinterpret_cast<u32*>(&sm.Ahi[row * AST + c0]) = hp;
          *reinterpret_cast<u32*>(&sm.Alo[row * AST + c0]) = lp;
          mx[nt][0] = fmaxf(mx[nt][0], val ? h0 : NEG_BIG);
          mx[nt][1] = fmaxf(mx[nt][1], val ? h1 : NEG_BIG);
        }
      }
    #pragma unroll
    for (int nt = 0; nt < 4; nt++)
      #pragma unroll
      for (int j = 0; j < 2; j++) {
        mx[nt][j] = fmaxf(mx[nt][j], __shfl_xor_sync(0xffffffffu, mx[nt][j], 4));
        mx[nt][j] = fmaxf(mx[nt][j], __shfl_xor_sync(0xffffffffu, mx[nt][j], 8));
        mx[nt][j] = fmaxf(mx[nt][j], __shfl_xor_sync(0xffffffffu, mx[nt][j], 16));
      }
    if (lane < 4) {
      #pragma unroll
      for (int nt = 0; nt < 4; nt++) {
        sm.pmax[warpM][CB + nt * 8 + qc * 2]     = mx[nt][0];
        sm.pmax[warpM][CB + nt * 8 + qc * 2 + 1] = mx[nt][1];
      }
    }
    __syncthreads();   // pmax + A(next input for GEMM2) visible

    // ---- GEMV partials: aggw = b2 + max(pmax0,pmax1) @ W2_bottom ----
    // 4 independent accumulators + deep unroll -> high MLP, halves the
    // L2-latency exposure of the 64 strided weight loads.
    {
      int e = tid & 127, h = tid >> 7;
      const float* wb = W2 + ((size_t)l * 256 + 128) * 128 + e;
      int d0 = h * 64;
      float a0 = h ? 0.f : __ldg(&b2[l * 128 + e]);
      float a1 = 0.f, a2 = 0.f, a3 = 0.f;
      #pragma unroll 16
      for (int dd = 0; dd < 64; dd += 4) {
        int d = d0 + dd;
        a0 = fmaf(fmaxf(sm.pmax[0][d],     sm.pmax[1][d]),
                  __ldg(&wb[(size_t)d * 128]), a0);
        a1 = fmaf(fmaxf(sm.pmax[0][d + 1], sm.pmax[1][d + 1]),
                  __ldg(&wb[(size_t)(d + 1) * 128]), a1);
        a2 = fmaf(fmaxf(sm.pmax[0][d + 2], sm.pmax[1][d + 2]),
                  __ldg(&wb[(size_t)(d + 2) * 128]), a2);
        a3 = fmaf(fmaxf(sm.pmax[0][d + 3], sm.pmax[1][d + 3]),
                  __ldg(&wb[(size_t)(d + 3) * 128]), a3);
      }
      sm.gpart[h][e] = (a0 + a1) + (a2 + a3);
    }
    CP_WAIT0();
    __syncthreads();   // B(W2top) + gpart visible

    // ---- GEMM2: acc init = aggw (gpart0+gpart1) ----
    #pragma unroll
    for (int nt = 0; nt < 4; nt++) {
      int c0 = CB + nt * 8 + qc * 2;
      cinit[nt * 2]     = sm.gpart[0][c0]     + sm.gpart[1][c0];
      cinit[nt * 2 + 1] = sm.gpart[0][c0 + 1] + sm.gpart[1][c0 + 1];
    }
    #pragma unroll
    for (int a = 0; a < 2; a++)
      #pragma unroll
      for (int b = 0; b < 4; b++)
        #pragma unroll
        for (int e = 0; e < 4; e++) acc[a][b][e] = cinit[b * 2 + (e & 1)];
    #pragma unroll
    for (int kt = 0; kt < 8; kt++) {
      u32 ah[2][4], al[2][4], bh[2][4], bl[2][4];
      #pragma unroll
      for (int mt = 0; mt < 2; mt++) {
        ldsm4(ah[mt][0], ah[mt][1], ah[mt][2], ah[mt][3], uAhi + aoff[mt] + kt * 32);
        ldsm4(al[mt][0], al[mt][1], al[mt][2], al[mt][3], uAlo + aoff[mt] + kt * 32);
      }
      #pragma unroll
      for (int p = 0; p < 2; p++) {
        ldsm4(bh[p][0], bh[p][1], bh[p][2], bh[p][3], uBhi + boff[p] + kt * 32);
        ldsm4(bl[p][0], bl[p][1], bl[p][2], bl[p][3], uBlo + boff[p] + kt * 32);
      }
      #pragma unroll
      for (int mt = 0; mt < 2; mt++)
        #pragma unroll
        for (int nt = 0; nt < 4; nt++) {
          int p = nt >> 1, h = (nt & 1) * 2;
          mmab(acc[mt][nt], ah[mt], bh[p][h], bh[p][h + 1]);
          mmab(acc[mt][nt], ah[mt], bl[p][h], bl[p][h + 1]);
          mmab(acc[mt][nt], al[mt], bh[p][h], bh[p][h + 1]);
        }
    }

    // RACE FIX: warps sharing warpM read the same A rows in GEMM2;
    // epilogue-2 overwrites those rows. Barrier before any A write.
    __syncthreads();

    // ---- epilogue 2: next-layer split OR final masked max (aggw already in acc) ----
    if (l < NL - 1) {
      #pragma unroll
      for (int mt = 0; mt < 2; mt++)
        #pragma unroll
        for (int hi = 0; hi < 2; hi++) {
          int row = RB + mt * 16 + qr + hi * 8;
          #pragma unroll
          for (int nt = 0; nt < 4; nt++) {
            int c0 = CB + nt * 8 + qc * 2;
            u32 hp, lp; split2(acc[mt][nt][2 * hi], acc[mt][nt][2 * hi + 1], hp, lp);
            *reinterpret_cast<u32*>(&sm.Ahi[row * AST + c0]) = hp;
            *reinterpret_cast<u32*>(&sm.Alo[row * AST + c0]) = lp;
          }
        }
      __syncthreads();   // A ready; B free (all warps finished GEMM2)
      copy_B(uBhi, &g_Bimg[(l + 1) * 2][0][0], tid);
      CP_COMMIT();
    } else {
      float mx2[4][2];
      #pragma unroll
      for (int nt = 0; nt < 4; nt++) { mx2[nt][0] = NEG_BIG; mx2[nt][1] = NEG_BIG; }
      #pragma unroll
      for (int mt = 0; mt < 2; mt++)
        #pragma unroll
        for (int hi = 0; hi < 2; hi++) {
          int row = RB + mt * 16 + qr + hi * 8;
          bool val = sm.valid[row] != 0;
          #pragma unroll
          for (int nt = 0; nt < 4; nt++) {
            mx2[nt][0] = fmaxf(mx2[nt][0], val ? acc[mt][nt][2 * hi]     : NEG_BIG);
            mx2[nt][1] = fmaxf(mx2[nt][1], val ? acc[mt][nt][2 * hi + 1] : NEG_BIG);
          }
        }
      #pragma unroll
      for (int nt = 0; nt < 4; nt++)
        #pragma unroll
        for (int j = 0; j < 2; j++) {
          mx2[nt][j] = fmaxf(mx2[nt][j], __shfl_xor_sync(0xffffffffu, mx2[nt][j], 4));
          mx2[nt][j] = fmaxf(mx2[nt][j], __shfl_xor_sync(0xffffffffu, mx2[nt][j], 8));
          mx2[nt][j] = fmaxf(mx2[nt][j], __shfl_xor_sync(0xffffffffu, mx2[nt][j], 16));
        }
      if (lane < 4) {
        #pragma unroll
        for (int nt = 0; nt < 4; nt++) {
          sm.pmax[warpM][CB + nt * 8 + qc * 2]     = mx2[nt][0];
          sm.pmax[warpM][CB + nt * 8 + qc * 2 + 1] = mx2[nt][1];
        }
      }
      __syncthreads();
      if (tid < 128) {
        float m = fmaxf(sm.pmax[0][tid], sm.pmax[1][tid]);
        if (!sm.pv) m = 0.f;
        out[(size_t)poly * 128 + tid] = m;
      }
    }
  }
}

extern "C" void kernel_launch(void* const* d_in, const int* in_sizes, int n_in,
                              void* d_out, int out_size) {
  const float*         x    = (const float*)d_in[0];
  const unsigned char* mask = (const unsigned char*)d_in[1];
  const float*         W1   = (const float*)d_in[2];
  const float*         b1   = (const float*)d_in[3];
  const float*         lng  = (const float*)d_in[4];
  const float*         lnb  = (const float*)d_in[5];
  const float*         W2   = (const float*)d_in[6];
  const float*         b2   = (const float*)d_in[7];
  float* out = (float*)d_out;

  int smem = (int)sizeof(Sm) + 128;
  (void)cudaFuncSetAttribute(polymma_kernel,
                             cudaFuncAttributeMaxDynamicSharedMemorySize, smem);

  prep_kernel<<<(NL * 2 * 128 * 128 + 255) / 256, 256>>>(W1, W2);
  polymma_kernel<<<2048, 256, smem>>>(x, mask, b1, lng, lnb, W2, b2, out);
}

// round 14
// speedup vs baseline: 2.6889x; 1.0834x over previous
#include <cuda_runtime.h>
#include <cuda_bf16.h>
#include <cstdint>

#define NL 3
#define AST 136                      // padded row stride (bf16 elems)
#define NEG_BIG (-3.402823466e38f)

typedef unsigned int u32;
typedef unsigned short u16;

// Pre-split weight images: [l*2+m][hi=0/lo=1][n*AST + k], bf16, [n][k]
__device__ __align__(16) u16 g_Bimg[NL * 2][2][128 * AST];

__device__ __forceinline__ u32 smaddr(const void* p) {
  u32 a; asm("{ .reg .u64 t; cvta.to.shared.u64 t, %1; cvt.u32.u64 %0, t; }"
             : "=r"(a) : "l"(p));
  return a;
}
__device__ __forceinline__ void ldsm4(u32& r0, u32& r1, u32& r2, u32& r3, u32 a) {
  asm volatile("ldmatrix.sync.aligned.m8n8.x4.shared.b16 {%0,%1,%2,%3}, [%4];"
               : "=r"(r0), "=r"(r1), "=r"(r2), "=r"(r3) : "r"(a));
}
__device__ __forceinline__ void mmab(float* c, const u32* a, u32 b0, u32 b1) {
  asm volatile(
    "mma.sync.aligned.m16n8k16.row.col.f32.bf16.bf16.f32 "
    "{%0,%1,%2,%3}, {%4,%5,%6,%7}, {%8,%9}, {%0,%1,%2,%3};"
    : "+f"(c[0]), "+f"(c[1]), "+f"(c[2]), "+f"(c[3])
    : "r"(a[0]), "r"(a[1]), "r"(a[2]), "r"(a[3]), "r"(b0), "r"(b1));
}
__device__ __forceinline__ void cpa16(u32 dst, const void* src) {
  asm volatile("cp.async.cg.shared.global [%0], [%1], 16;" :: "r"(dst), "l"(src) : "memory");
}
#define CP_COMMIT() asm volatile("cp.async.commit_group;" ::: "memory")
#define CP_WAIT0()  asm volatile("cp.async.wait_group 0;" ::: "memory")

// hi/lo bf16 split (rn rounding, identical to __float2bfloat16)
__device__ __forceinline__ void split2(float f0, float f1, u32& hp, u32& lp) {
  u32 h;
  asm("cvt.rn.bf16x2.f32 %0, %1, %2;" : "=r"(h) : "f"(f1), "f"(f0));
  float h0 = __uint_as_float(h << 16);
  float h1 = __uint_as_float(h & 0xffff0000u);
  float l0 = f0 - h0, l1 = f1 - h1;
  asm("cvt.rn.bf16x2.f32 %0, %1, %2;" : "=r"(lp) : "f"(l1), "f"(l0));
  hp = h;
}

// ---------------- prep: split fp32 weights into bf16 hi/lo [n][k] images ----------------
__global__ void prep_kernel(const float* __restrict__ W1, const float* __restrict__ W2) {
  int id = blockIdx.x * blockDim.x + threadIdx.x;
  if (id >= NL * 2 * 128 * 128) return;
  int n = id & 127, k = (id >> 7) & 127, m = (id >> 14) & 1, l = id >> 15;
  float w = m ? W2[((size_t)l * 256 + k) * 128 + n]
              : W1[((size_t)l * 128 + k) * 128 + n];
  __nv_bfloat16 hi = __float2bfloat16(w);
  __nv_bfloat16 lo = __float2bfloat16(w - __bfloat162float(hi));
  g_Bimg[l * 2 + m][0][n * AST + k] = __bfloat16_as_ushort(hi);
  g_Bimg[l * 2 + m][1][n * AST + k] = __bfloat16_as_ushort(lo);
}

// ---------------- main fused kernel: 1 poly/CTA, 4 warps x (16 rows, 128 cols),
// activations register-chained (GEMM1 D-frag == GEMM2 A-frag), 3 CTAs/SM ----------------
struct Sm {
  u16 B[2][128 * AST];             // hi,lo of current weight matrix (69632 B)
  float pmax[4][128];
  float agg[128];
  float aggw[128];
  float bias[128], g[128], beta[128];
  unsigned char valid[64];
  int pv;
  u32 det[2];
};

__device__ __forceinline__ void copy_B(u32 dst, const u16* src, int tid) {
  const char* s = reinterpret_cast<const char*>(src);
  #pragma unroll
  for (int i = tid; i < 4352; i += 128) cpa16(dst + i * 16, s + (size_t)i * 16);
}

// 128x128x128 GEMM, A in registers (hh/hl, frag layout), B in smem.
// acc[nt][0..3]: c0=(qr,8nt+2qc) c1=(qr,+1) c2=(qr+8,8nt+2qc) c3=(qr+8,+1)
__device__ __forceinline__ void run_gemm(
    float (*acc)[4], const u32* hh, const u32* hl,
    u32 uBhi, u32 uBlo, u32 boff0)
{
  #pragma unroll
  for (int kt = 0; kt < 8; kt++) {
    const u32* ah = &hh[4 * kt];    // A-frag = D-frags of nt 2kt,2kt+1 (identity)
    const u32* al = &hl[4 * kt];
    #pragma unroll
    for (int p = 0; p < 8; p++) {
      u32 bh[4], bl[4];
      u32 ba = boff0 + (u32)(p * 16 * AST * 2) + (u32)(kt * 32);
      ldsm4(bh[0], bh[1], bh[2], bh[3], uBhi + ba);
      ldsm4(bl[0], bl[1], bl[2], bl[3], uBlo + ba);
      mmab(acc[2 * p],     ah, bh[0], bh[1]);
      mmab(acc[2 * p],     ah, bl[0], bl[1]);
      mmab(acc[2 * p],     al, bh[0], bh[1]);
      mmab(acc[2 * p + 1], ah, bh[2], bh[3]);
      mmab(acc[2 * p + 1], ah, bl[2], bl[3]);
      mmab(acc[2 * p + 1], al, bh[2], bh[3]);
    }
  }
}

__global__ void __launch_bounds__(128, 3) polyreg_kernel(
    const float* __restrict__ x, const unsigned char* __restrict__ mask,
    const float* __restrict__ b1, const float* __restrict__ lng,
    const float* __restrict__ lnb, const float* __restrict__ W2,
    const float* __restrict__ b2, float* __restrict__ out)
{
  extern __shared__ unsigned char smraw[];
  uintptr_t sp = (reinterpret_cast<uintptr_t>(smraw) + 127) & ~(uintptr_t)127;
  Sm& sm = *reinterpret_cast<Sm*>(sp);

  const int tid = threadIdx.x;
  const int wid = tid >> 5, lane = tid & 31;
  const int qr = lane >> 2, qc = lane & 3;
  const int row0 = wid * 16 + qr, row1 = row0 + 8;
  const int poly = blockIdx.x;

  const u32 uBhi = smaddr(sm.B[0]);
  const u32 uBlo = uBhi + 128 * AST * 2;

  // ldmatrix lane-address base for B (proven mapping from R10-R12)
  const int nrow = (lane & 7) + (lane >> 4) * 8;
  const int kcol = ((lane >> 3) & 1) * 8;
  const u32 boff0 = (u32)((nrow * AST + kcol) * 2);

  // kick layer-0 W1 copy immediately (overlaps with everything below)
  copy_B(uBhi, &g_Bimg[0][0][0], tid);
  CP_COMMIT();

  if (tid == 0) sm.pv = 0;
  if (tid < 2) sm.det[tid] = 0u;
  __syncthreads();

  // ---- mask dtype detection (proven R5/R7/R10) ----
  {
    const u32* mw = reinterpret_cast<const u32*>(mask);
    u32 o123 = 0, o23 = 0;
    for (int j = tid; j < 1024; j += 128) {
      u32 w = mw[j];
      o123 |= (w >> 8);
      o23  |= (w >> 16);
    }
    if (o123) atomicOr(&sm.det[0], o123 & 0xffffffu);
    if (o23)  atomicOr(&sm.det[1], o23 & 0xffffu);
  }
  __syncthreads();
  const int mmode = (sm.det[1] & 0xF0F0u) ? 1 : (sm.det[0] ? 0 : 1);

  if (tid < 64) {
    int midx = poly * 64 + tid;
    unsigned char m;
    if (mmode == 0) m = mask[midx] ? 1 : 0;
    else m = (reinterpret_cast<const u32*>(mask)[midx] != 0u) ? 1 : 0;
    sm.valid[tid] = m;
    if (m) atomicOr(&sm.pv, 1);
  }
  __syncthreads();
  if (tid < 64 && !sm.pv) sm.valid[tid] = 1;   // neutralize fully-invalid poly
  __syncthreads();

  // ---- prologue: x -> hh/hl registers in A-fragment layout ----
  u32 hh[32], hl[32];                  // [nt*2+i]: i=0 row qr, i=1 row qr+8
  {
    const float* xp = x + (size_t)poly * 64 * 128;
    const bool pvok = sm.pv != 0;
    #pragma unroll
    for (int nt = 0; nt < 16; nt++) {
      int c0 = 8 * nt + 2 * qc;
      float2 v0 = make_float2(0.f, 0.f), v1 = v0;
      if (pvok) {
        v0 = *reinterpret_cast<const float2*>(xp + row0 * 128 + c0);
        v1 = *reinterpret_cast<const float2*>(xp + row1 * 128 + c0);
      }
      split2(v0.x, v0.y, hh[nt * 2],     hl[nt * 2]);
      split2(v1.x, v1.y, hh[nt * 2 + 1], hl[nt * 2 + 1]);
    }
  }

  const unsigned char val0 = sm.valid[row0], val1 = sm.valid[row1];
  float acc[16][4];

  for (int l = 0; l < NL; l++) {
    if (tid < 128) {
      sm.bias[tid] = b1[l * 128 + tid];
      sm.g[tid]    = lng[l * 128 + tid];
      sm.beta[tid] = lnb[l * 128 + tid];
    }
    CP_WAIT0();
    __syncthreads();               // [bar A] B=W1 + params ready

    // ---- GEMM1 (acc init = bias) ----
    #pragma unroll
    for (int nt = 0; nt < 16; nt++) {
      float b0 = sm.bias[8 * nt + 2 * qc], b1v = sm.bias[8 * nt + 2 * qc + 1];
      acc[nt][0] = b0; acc[nt][1] = b1v; acc[nt][2] = b0; acc[nt][3] = b1v;
    }
    run_gemm(acc, hh, hl, uBhi, uBlo, boff0);

    // ---- epilogue 1: warp-local LN + ReLU -> hh/hl; masked col-max -> pmax ----
    {
      float s0 = 0.f, q0 = 0.f, s1 = 0.f, q1 = 0.f;
      #pragma unroll
      for (int nt = 0; nt < 16; nt++) {
        s0 += acc[nt][0] + acc[nt][1];
        q0 += acc[nt][0] * acc[nt][0] + acc[nt][1] * acc[nt][1];
        s1 += acc[nt][2] + acc[nt][3];
        q1 += acc[nt][2] * acc[nt][2] + acc[nt][3] * acc[nt][3];
      }
      s0 += __shfl_xor_sync(0xffffffffu, s0, 1); s0 += __shfl_xor_sync(0xffffffffu, s0, 2);
      q0 += __shfl_xor_sync(0xffffffffu, q0, 1); q0 += __shfl_xor_sync(0xffffffffu, q0, 2);
      s1 += __shfl_xor_sync(0xffffffffu, s1, 1); s1 += __shfl_xor_sync(0xffffffffu, s1, 2);
      q1 += __shfl_xor_sync(0xffffffffu, q1, 1); q1 += __shfl_xor_sync(0xffffffffu, q1, 2);
      float mean0 = s0 * (1.f / 128.f);
      float inv0  = rsqrtf(fmaf(q0, 1.f / 128.f, -mean0 * mean0) + 1e-5f);
      float mean1 = s1 * (1.f / 128.f);
      float inv1  = rsqrtf(fmaf(q1, 1.f / 128.f, -mean1 * mean1) + 1e-5f);

      float mx0[16], mx1[16];
      #pragma unroll
      for (int nt = 0; nt < 16; nt++) {
        int c0 = 8 * nt + 2 * qc;
        float gg0 = sm.g[c0], gg1 = sm.g[c0 + 1];
        float bb0 = sm.beta[c0], bb1 = sm.beta[c0 + 1];
        float h0 = fmaxf(fmaf((acc[nt][0] - mean0) * inv0, gg0, bb0), 0.f);
        float h1 = fmaxf(fmaf((acc[nt][1] - mean0) * inv0, gg1, bb1), 0.f);
        float h2 = fmaxf(fmaf((acc[nt][2] - mean1) * inv1, gg0, bb0), 0.f);
        float h3 = fmaxf(fmaf((acc[nt][3] - mean1) * inv1, gg1, bb1), 0.f);
        split2(h0, h1, hh[nt * 2],     hl[nt * 2]);
        split2(h2, h3, hh[nt * 2 + 1], hl[nt * 2 + 1]);
        mx0[nt] = fmaxf(val0 ? h0 : NEG_BIG, val1 ? h2 : NEG_BIG);
        mx1[nt] = fmaxf(val0 ? h1 : NEG_BIG, val1 ? h3 : NEG_BIG);
      }
      #pragma unroll
      for (int nt = 0; nt < 16; nt++) {
        #pragma unroll
        for (int m = 4; m <= 16; m <<= 1) {
          mx0[nt] = fmaxf(mx0[nt], __shfl_xor_sync(0xffffffffu, mx0[nt], m));
          mx1[nt] = fmaxf(mx1[nt], __shfl_xor_sync(0xffffffffu, mx1[nt], m));
        }
      }
      if (qr == 0) {
        #pragma unroll
        for (int nt = 0; nt < 16; nt++) {
          sm.pmax[wid][8 * nt + 2 * qc]     = mx0[nt];
          sm.pmax[wid][8 * nt + 2 * qc + 1] = mx1[nt];
        }
      }
    }
    __syncthreads();               // [bar B] GEMM1 B reads done + pmax visible

    // agg = max over 4 warps; stage W2top
    sm.agg[tid] = fmaxf(fmaxf(sm.pmax[0][tid], sm.pmax[1][tid]),
                        fmaxf(sm.pmax[2][tid], sm.pmax[3][tid]));
    copy_B(uBhi, &g_Bimg[l * 2 + 1][0][0], tid);
    CP_COMMIT();
    CP_WAIT0();
    __syncthreads();               // [bar C] B=W2top + agg visible

    // ---- GEMM2 (acc init = 0; aggw added later) ----
    #pragma unroll
    for (int nt = 0; nt < 16; nt++) {
      acc[nt][0] = 0.f; acc[nt][1] = 0.f; acc[nt][2] = 0.f; acc[nt][3] = 0.f;
    }
    run_gemm(acc, hh, hl, uBhi, uBlo, boff0);

    // ---- GEMV: aggw[e] = b2[e] + agg @ W2_bottom (1 col/thread, coalesced) ----
    {
      const float* wb = W2 + ((size_t)l * 256 + 128) * 128 + tid;
      float a0 = __ldg(&b2[l * 128 + tid]);
      float a1 = 0.f, a2 = 0.f, a3 = 0.f;
      #pragma unroll 8
      for (int d = 0; d < 128; d += 4) {
        a0 = fmaf(sm.agg[d],     __ldg(&wb[(size_t)d * 128]),       a0);
        a1 = fmaf(sm.agg[d + 1], __ldg(&wb[(size_t)(d + 1) * 128]), a1);
        a2 = fmaf(sm.agg[d + 2], __ldg(&wb[(size_t)(d + 2) * 128]), a2);
        a3 = fmaf(sm.agg[d + 3], __ldg(&wb[(size_t)(d + 3) * 128]), a3);
      }
      sm.aggw[tid] = (a0 + a1) + (a2 + a3);
    }
    __syncthreads();               // [bar D] aggw visible + GEMM2 B reads done

    // ---- epilogue 2 ----
    if (l < NL - 1) {
      #pragma unroll
      for (int nt = 0; nt < 16; nt++) {
        int c0 = 8 * nt + 2 * qc;
        float w0 = sm.aggw[c0], w1 = sm.aggw[c0 + 1];
        split2(acc[nt][0] + w0, acc[nt][1] + w1, hh[nt * 2],     hl[nt * 2]);
        split2(acc[nt][2] + w0, acc[nt][3] + w1, hh[nt * 2 + 1], hl[nt * 2 + 1]);
      }
      copy_B(uBhi, &g_Bimg[(l + 1) * 2][0][0], tid);   // B free after bar D
      CP_COMMIT();
    } else {
      float mx0[16], mx1[16];
      #pragma unroll
      for (int nt = 0; nt < 16; nt++) {
        mx0[nt] = fmaxf(val0 ? acc[nt][0] : NEG_BIG, val1 ? acc[nt][2] : NEG_BIG);
        mx1[nt] = fmaxf(val0 ? acc[nt][1] : NEG_BIG, val1 ? acc[nt][3] : NEG_BIG);
      }
      #pragma unroll
      for (int nt = 0; nt < 16; nt++) {
        #pragma unroll
        for (int m = 4; m <= 16; m <<= 1) {
          mx0[nt] = fmaxf(mx0[nt], __shfl_xor_sync(0xffffffffu, mx0[nt], m));
          mx1[nt] = fmaxf(mx1[nt], __shfl_xor_sync(0xffffffffu, mx1[nt], m));
        }
      }
      if (qr == 0) {
        #pragma unroll
        for (int nt = 0; nt < 16; nt++) {
          sm.pmax[wid][8 * nt + 2 * qc]     = mx0[nt];
          sm.pmax[wid][8 * nt + 2 * qc + 1] = mx1[nt];
        }
      }
      __syncthreads();
      float m = fmaxf(fmaxf(sm.pmax[0][tid], sm.pmax[1][tid]),
                      fmaxf(sm.pmax[2][tid], sm.pmax[3][tid])) + sm.aggw[tid];
      if (!sm.pv) m = 0.f;
      out[(size_t)poly * 128 + tid] = m;
    }
  }
}

extern "C" void kernel_launch(void* const* d_in, const int* in_sizes, int n_in,
                              void* d_out, int out_size) {
  const float*         x    = (const float*)d_in[0];
  const unsigned char* mask = (const unsigned char*)d_in[1];
  const float*         W1   = (const float*)d_in[2];
  const float*         b1   = (const float*)d_in[3];
  const float*         lng  = (const float*)d_in[4];
  const float*         lnb  = (const float*)d_in[5];
  const float*         W2   = (const float*)d_in[6];
  const float*         b2   = (const float*)d_in[7];
  float* out = (float*)d_out;

  int smem = (int)sizeof(Sm) + 128;
  (void)cudaFuncSetAttribute(polyreg_kernel,
                             cudaFuncAttributeMaxDynamicSharedMemorySize, smem);

  prep_kernel<<<(NL * 2 * 128 * 128 + 255) / 256, 256>>>(W1, W2);
  polyreg_kernel<<<2048, 128, smem>>>(x, mask, b1, lng, lnb, W2, b2, out);
}